// round 1
// baseline (speedup 1.0000x reference)
#include <cuda_runtime.h>
#include <cstddef>

#define Hh 512
#define Ww 512
#define KK 8
#define HWp (Hh*Ww)

typedef unsigned long long ull;

// ---------------- scratch (static device globals; no allocations) ----------------
__device__ float g_t1[KK * HWp * 32];   // sup conv1 out (relu)      256 MB
__device__ float g_fm[KK * HWp * 64];   // [k][y][x][64]: feat|fc    512 MB
__device__ float g_t2[KK * HWp * 64];   // mpn conv1 out (relu)      512 MB
__device__ float g_fuse[HWp * KK];      // fused [y][x][k]             8 MB
__device__ float g_u1[HWp * 32];        // unet conv1 out             32 MB

// ---------------- packed fp32x2 helpers (Blackwell FFMA2 path) ----------------
__device__ __forceinline__ ull pack2(float v) {
    ull r; asm("mov.b64 %0, {%1, %1};" : "=l"(r) : "f"(v)); return r;
}
__device__ __forceinline__ float2 unpack2(ull v) {
    float2 f; asm("mov.b64 {%0, %1}, %2;" : "=f"(f.x), "=f"(f.y) : "l"(v)); return f;
}
__device__ __forceinline__ void fma2(ull &d, ull a, ull b) {
    asm("fma.rn.f32x2 %0, %1, %2, %0;" : "+l"(d) : "l"(a), "l"(b));
}

// =======================================================================
// MLP kernel: per-sample radiance mapping, all weights in smem.
// 256 threads, 64 samples per tile; thread t: sample s=t%64, couts [32g,32g+32)
// =======================================================================
#define AP 133   // activation row stride (odd -> conflict-free)
#define OFF_W1 0
#define OFF_W2 (OFF_W1 + 3*128)
#define OFF_W3 (OFF_W2 + 128*128)
#define OFF_W4 (OFF_W3 + 131*128)
#define OFF_B1 (OFF_W4 + 128*32)
#define OFF_B2 (OFF_B1 + 128)
#define OFF_B3 (OFF_B2 + 128)
#define OFF_B4 (OFF_B3 + 128)
#define OFF_A  (OFF_B4 + 32)
#define OFF_Bb (OFF_A + 64*AP)
#define OFF_M  (OFF_Bb + 64*AP)
#define MLP_SMEM ((OFF_M + 64) * 4)

__device__ __forceinline__ void mlp_dense128(const float* __restrict__ in, int Kin,
                                             const float* __restrict__ sW,
                                             const float* __restrict__ sB,
                                             int j0, float* __restrict__ outp)
{
    ull acc[16];
    const ull* bb = (const ull*)(sB + j0);
#pragma unroll
    for (int i = 0; i < 16; i++) acc[i] = bb[i];
#pragma unroll 4
    for (int k = 0; k < Kin; k++) {
        ull a2 = pack2(in[k]);
        const ulonglong2* w = (const ulonglong2*)(sW + k * 128 + j0);
#pragma unroll
        for (int i = 0; i < 8; i++) { fma2(acc[2*i], a2, w[i].x); fma2(acc[2*i+1], a2, w[i].y); }
    }
#pragma unroll
    for (int i = 0; i < 16; i++) {
        float2 v = unpack2(acc[i]);
        outp[2*i]   = fmaxf(v.x, 0.f);
        outp[2*i+1] = fmaxf(v.y, 0.f);
    }
}

__global__ __launch_bounds__(256, 1)
void mlp_kernel(const float* __restrict__ ray, const float* __restrict__ zb,
                const float* __restrict__ W1, const float* __restrict__ b1,
                const float* __restrict__ W2, const float* __restrict__ b2,
                const float* __restrict__ W3, const float* __restrict__ b3,
                const float* __restrict__ W4, const float* __restrict__ b4,
                float* __restrict__ fm)
{
    extern __shared__ float sh[];
    const int tid = threadIdx.x;

    // stage all weights + biases once per block
    for (int i = tid; i < 3*128;   i += 256) sh[OFF_W1 + i] = W1[i];
    for (int i = tid; i < 128*128; i += 256) sh[OFF_W2 + i] = W2[i];
    for (int i = tid; i < 131*128; i += 256) sh[OFF_W3 + i] = W3[i];
    for (int i = tid; i < 128*32;  i += 256) sh[OFF_W4 + i] = W4[i];
    if (tid < 128) { sh[OFF_B1+tid] = b1[tid]; sh[OFF_B2+tid] = b2[tid]; sh[OFF_B3+tid] = b3[tid]; }
    if (tid < 32)  sh[OFF_B4 + tid] = b4[tid];
    __syncthreads();

    const int s  = tid & 63;
    const int g  = tid >> 6;     // 0..3
    const int j0 = g * 32;
    const int NTILE = (KK * HWp) / 64;

    for (int tile = blockIdx.x; tile < NTILE; tile += gridDim.x) {
        // stage 0: xyz = o + d*z/cos ; dirs ; mask
        if (tid < 64) {
            int sid = tile * 64 + tid;
            int kk  = sid / HWp;
            int pix = sid - kk * HWp;
            const float* r = ray + (size_t)pix * 7;
            float z   = zb[(size_t)pix * KK + kk];
            float t   = z / r[6];
            float* Ar = sh + OFF_A + tid * AP;
            Ar[0] = r[0] + r[3] * t;
            Ar[1] = r[1] + r[4] * t;
            Ar[2] = r[2] + r[5] * t;
            Ar[128] = r[3]; Ar[129] = r[4]; Ar[130] = r[5];
            sh[OFF_M + tid] = (z > 0.f) ? 1.f : 0.f;
        }
        __syncthreads();
        // layer1: A[0..2] -> B (relu)
        mlp_dense128(sh + OFF_A + s*AP, 3,   sh + OFF_W1, sh + OFF_B1, j0, sh + OFF_Bb + s*AP + j0);
        __syncthreads();
        // layer2: B -> A[0..127] (relu); A[128..130] keeps dirs
        mlp_dense128(sh + OFF_Bb + s*AP, 128, sh + OFF_W2, sh + OFF_B2, j0, sh + OFF_A + s*AP + j0);
        __syncthreads();
        // layer3: A[0..130] -> B (relu)
        mlp_dense128(sh + OFF_A + s*AP, 131, sh + OFF_W3, sh + OFF_B3, j0, sh + OFF_Bb + s*AP + j0);
        __syncthreads();
        // layer4: B -> global feat (32 couts, 8 per thread), masked
        {
            const int j4 = g * 8;
            ull acc[4];
            const ull* bb = (const ull*)(sh + OFF_B4 + j4);
#pragma unroll
            for (int i = 0; i < 4; i++) acc[i] = bb[i];
            const float* in = sh + OFF_Bb + s * AP;
#pragma unroll 4
            for (int k = 0; k < 128; k++) {
                ull a2 = pack2(in[k]);
                const ulonglong2* w = (const ulonglong2*)(sh + OFF_W4 + k * 32 + j4);
                fma2(acc[0], a2, w[0].x); fma2(acc[1], a2, w[0].y);
                fma2(acc[2], a2, w[1].x); fma2(acc[3], a2, w[1].y);
            }
            float mf = sh[OFF_M + s];
            size_t sid = (size_t)tile * 64 + s;
            float* op = fm + sid * 64 + j4;
            float2 v0 = unpack2(acc[0]), v1 = unpack2(acc[1]);
            float2 v2 = unpack2(acc[2]), v3 = unpack2(acc[3]);
            float4 o0 = make_float4(v0.x*mf, v0.y*mf, v1.x*mf, v1.y*mf);
            float4 o1 = make_float4(v2.x*mf, v2.y*mf, v3.x*mf, v3.y*mf);
            *(float4*)op       = o0;
            *(float4*)(op + 4) = o1;
        }
        __syncthreads();
    }
}

// =======================================================================
// Generic direct 3x3 SAME conv: 16x16 pixel tile, cin-chunked smem staging.
// thread = 1 pixel x COUT couts (FFMA2-packed accumulators)
// =======================================================================
template<int CIN, int CHUNK, int COUT, bool RELU>
__global__ __launch_bounds__(256)
void conv3x3_kernel(const float* __restrict__ in, const float* __restrict__ wgt,
                    const float* __restrict__ bias, float* __restrict__ out,
                    int in_batch_stride, int in_pix_stride, int in_ch_per_n,
                    int out_batch_stride, int out_pix_stride, int out_ch_off)
{
    constexpr int SP = CHUNK + 1;
    extern __shared__ float sh[];
    float* s_in = sh;                 // 324 * SP
    float* s_w  = sh + 324 * SP;      // 9 * CHUNK * COUT

    const int tid = threadIdx.x;
    const int tx = tid & 15, ty = tid >> 4;
    const int gx = blockIdx.x * 16, gy = blockIdx.y * 16;
    const int n  = blockIdx.z;
    const size_t nb = (size_t)n * in_batch_stride + (size_t)n * in_ch_per_n;

    ull acc[COUT / 2];
    {
        const ull* b2 = (const ull*)bias;
#pragma unroll
        for (int i = 0; i < COUT/2; i++) acc[i] = __ldg(&b2[i]);
    }

    for (int c0 = 0; c0 < CIN; c0 += CHUNK) {
        for (int idx = tid; idx < 324 * CHUNK; idx += 256) {
            int p = idx / CHUNK, c = idx - p * CHUNK;
            int py = p / 18, px = p - py * 18;
            int iy = gy - 1 + py, ix = gx - 1 + px;
            float v = 0.f;
            if ((unsigned)iy < Hh && (unsigned)ix < Ww)
                v = in[nb + (size_t)(iy * Ww + ix) * in_pix_stride + c0 + c];
            s_in[p * SP + c] = v;
        }
        for (int idx = tid; idx < 9 * CHUNK * COUT; idx += 256) {
            int tap = idx / (CHUNK * COUT);
            int r   = idx - tap * CHUNK * COUT;
            int c   = r / COUT, co = r - c * COUT;
            s_w[idx] = wgt[(size_t)(tap * CIN + c0 + c) * COUT + co];
        }
        __syncthreads();
#pragma unroll
        for (int tap = 0; tap < 9; tap++) {
            int ky = tap / 3, kx = tap - ky * 3;
            const float* ip = s_in + ((ty + ky) * 18 + tx + kx) * SP;
            const ulonglong2* wp = (const ulonglong2*)(s_w + tap * CHUNK * COUT);
#pragma unroll 2
            for (int c = 0; c < CHUNK; c++) {
                ull a2 = pack2(ip[c]);
                const ulonglong2* w = wp + c * (COUT / 4);
#pragma unroll
                for (int i = 0; i < COUT/4; i++) { fma2(acc[2*i], a2, w[i].x); fma2(acc[2*i+1], a2, w[i].y); }
            }
        }
        __syncthreads();
    }

    float* op = out + (size_t)n * out_batch_stride
                    + (size_t)((gy + ty) * Ww + gx + tx) * out_pix_stride + out_ch_off;
#pragma unroll
    for (int i = 0; i < COUT/4; i++) {
        float2 v0 = unpack2(acc[2*i]), v1 = unpack2(acc[2*i+1]);
        float4 o = make_float4(v0.x, v0.y, v1.x, v1.y);
        if (RELU) { o.x = fmaxf(o.x,0.f); o.y = fmaxf(o.y,0.f); o.z = fmaxf(o.z,0.f); o.w = fmaxf(o.w,0.f); }
        *(float4*)(op + 4*i) = o;
    }
}

// =======================================================================
// Fused MPN conv2 + sigmoid + cumprod-alpha compositing -> fuse[y][x][k]
// (conv body: CIN=64, CHUNK=16, COUT=64 over g_t2)
// =======================================================================
__global__ __launch_bounds__(256)
void mpn2_fuse_kernel(const float* __restrict__ wgt, const float* __restrict__ bias)
{
    constexpr int CIN = 64, CHUNK = 16, COUT = 64, SP = CHUNK + 1;
    extern __shared__ float sh[];
    float* s_in = sh;
    float* s_w  = sh + 324 * SP;

    const int tid = threadIdx.x;
    const int tx = tid & 15, ty = tid >> 4;
    const int gx = blockIdx.x * 16, gy = blockIdx.y * 16;
    const int n  = blockIdx.z;

    ull acc[COUT / 2];
    {
        const ull* b2 = (const ull*)bias;
#pragma unroll
        for (int i = 0; i < COUT/2; i++) acc[i] = __ldg(&b2[i]);
    }

    for (int c0 = 0; c0 < CIN; c0 += CHUNK) {
        for (int idx = tid; idx < 324 * CHUNK; idx += 256) {
            int p = idx / CHUNK, c = idx - p * CHUNK;
            int py = p / 18, px = p - py * 18;
            int iy = gy - 1 + py, ix = gx - 1 + px;
            float v = 0.f;
            if ((unsigned)iy < Hh && (unsigned)ix < Ww)
                v = g_t2[((size_t)n * HWp + (size_t)(iy * Ww + ix)) * 64 + c0 + c];
            s_in[p * SP + c] = v;
        }
        for (int idx = tid; idx < 9 * CHUNK * COUT; idx += 256) {
            int tap = idx / (CHUNK * COUT);
            int r   = idx - tap * CHUNK * COUT;
            int c   = r / COUT, co = r - c * COUT;
            s_w[idx] = wgt[(size_t)(tap * CIN + c0 + c) * COUT + co];
        }
        __syncthreads();
#pragma unroll
        for (int tap = 0; tap < 9; tap++) {
            int ky = tap / 3, kx = tap - ky * 3;
            const float* ip = s_in + ((ty + ky) * 18 + tx + kx) * SP;
            const ulonglong2* wp = (const ulonglong2*)(s_w + tap * CHUNK * COUT);
#pragma unroll 2
            for (int c = 0; c < CHUNK; c++) {
                ull a2 = pack2(ip[c]);
                const ulonglong2* w = wp + c * (COUT / 4);
#pragma unroll
                for (int i = 0; i < COUT/4; i++) { fma2(acc[2*i], a2, w[i].x); fma2(acc[2*i+1], a2, w[i].y); }
            }
        }
        __syncthreads();
    }

    // epilogue: m = sigmoid(logits); alpha cumprod; fuse = sum fm*m*alpha
    const int pix = (gy + ty) * Ww + gx + tx;
    const float2* f2 = (const float2*)(g_fm + ((size_t)n * HWp + pix) * 64);
    float alpha = 1.f, fuse = 0.f;
#pragma unroll
    for (int i = 0; i < 32; i++) {
        float2 v  = unpack2(acc[i]);
        float2 fv = __ldg(&f2[i]);
        float m0 = 1.f / (1.f + __expf(-v.x));
        fuse += fv.x * m0 * alpha;  alpha *= (1.f - m0);
        float m1 = 1.f / (1.f + __expf(-v.y));
        fuse += fv.y * m1 * alpha;  alpha *= (1.f - m1);
    }
    g_fuse[(size_t)pix * KK + n] = fuse;
}

// =======================================================================
// unet conv2: 32 -> 3 (no relu) -> final image
// =======================================================================
__global__ __launch_bounds__(256)
void unet2_kernel(const float* __restrict__ in, const float* __restrict__ wgt,
                  const float* __restrict__ bias, float* __restrict__ out)
{
    constexpr int CIN = 32, CHUNK = 16, SP = CHUNK + 1;
    __shared__ float s_in[324 * SP];
    __shared__ float s_w[9 * CHUNK * 3];

    const int tid = threadIdx.x;
    const int tx = tid & 15, ty = tid >> 4;
    const int gx = blockIdx.x * 16, gy = blockIdx.y * 16;

    float acc0 = __ldg(&bias[0]), acc1 = __ldg(&bias[1]), acc2 = __ldg(&bias[2]);

    for (int c0 = 0; c0 < CIN; c0 += CHUNK) {
        for (int idx = tid; idx < 324 * CHUNK; idx += 256) {
            int p = idx / CHUNK, c = idx - p * CHUNK;
            int py = p / 18, px = p - py * 18;
            int iy = gy - 1 + py, ix = gx - 1 + px;
            float v = 0.f;
            if ((unsigned)iy < Hh && (unsigned)ix < Ww)
                v = in[(size_t)(iy * Ww + ix) * CIN + c0 + c];
            s_in[p * SP + c] = v;
        }
        for (int idx = tid; idx < 9 * CHUNK * 3; idx += 256) {
            int tap = idx / (CHUNK * 3);
            int r   = idx - tap * CHUNK * 3;
            int c   = r / 3, co = r - c * 3;
            s_w[idx] = wgt[(size_t)(tap * CIN + c0 + c) * 3 + co];
        }
        __syncthreads();
#pragma unroll
        for (int tap = 0; tap < 9; tap++) {
            int ky = tap / 3, kx = tap - ky * 3;
            const float* ip = s_in + ((ty + ky) * 18 + tx + kx) * SP;
            const float* wp = s_w + tap * CHUNK * 3;
#pragma unroll
            for (int c = 0; c < CHUNK; c++) {
                float a = ip[c];
                acc0 += a * wp[c*3 + 0];
                acc1 += a * wp[c*3 + 1];
                acc2 += a * wp[c*3 + 2];
            }
        }
        __syncthreads();
    }
    float* op = out + (size_t)((gy + ty) * Ww + gx + tx) * 3;
    op[0] = acc0; op[1] = acc1; op[2] = acc2;
}

// =======================================================================
extern "C" void kernel_launch(void* const* d_in, const int* in_sizes, int n_in,
                              void* d_out, int out_size)
{
    const float* colors = (const float*)d_in[0];
    const float* ray    = (const float*)d_in[1];
    const float* zbufs  = (const float*)d_in[2];
    const float* W1 = (const float*)d_in[3];  const float* b1 = (const float*)d_in[4];
    const float* W2 = (const float*)d_in[5];  const float* b2 = (const float*)d_in[6];
    const float* W3 = (const float*)d_in[7];  const float* b3 = (const float*)d_in[8];
    const float* W4 = (const float*)d_in[9];  const float* b4 = (const float*)d_in[10];
    const float* k_sup1 = (const float*)d_in[11]; const float* b_sup1 = (const float*)d_in[12];
    const float* k_sup2 = (const float*)d_in[13]; const float* b_sup2 = (const float*)d_in[14];
    const float* k_mpn1 = (const float*)d_in[15]; const float* b_mpn1 = (const float*)d_in[16];
    const float* k_mpn2 = (const float*)d_in[17]; const float* b_mpn2 = (const float*)d_in[18];
    const float* k_un1  = (const float*)d_in[19]; const float* b_un1  = (const float*)d_in[20];
    const float* k_un2  = (const float*)d_in[21]; const float* b_un2  = (const float*)d_in[22];

    float *t1, *fm, *t2, *fuse, *u1;
    cudaGetSymbolAddress((void**)&t1,   g_t1);
    cudaGetSymbolAddress((void**)&fm,   g_fm);
    cudaGetSymbolAddress((void**)&t2,   g_t2);
    cudaGetSymbolAddress((void**)&fuse, g_fuse);
    cudaGetSymbolAddress((void**)&u1,   g_u1);

    const int SUP1_SMEM = (324*4  + 9*3*32)  * 4;
    const int SUP2_SMEM = (324*17 + 9*16*32) * 4;
    const int MPN_SMEM  = (324*17 + 9*16*64) * 4;
    const int UN1_SMEM  = (324*9  + 9*8*32)  * 4;

    cudaFuncSetAttribute(mlp_kernel, cudaFuncAttributeMaxDynamicSharedMemorySize, MLP_SMEM);
    cudaFuncSetAttribute(conv3x3_kernel<64,16,64,true>, cudaFuncAttributeMaxDynamicSharedMemorySize, MPN_SMEM);
    cudaFuncSetAttribute(mpn2_fuse_kernel, cudaFuncAttributeMaxDynamicSharedMemorySize, MPN_SMEM);
    cudaFuncSetAttribute(conv3x3_kernel<32,16,32,false>, cudaFuncAttributeMaxDynamicSharedMemorySize, SUP2_SMEM);

    dim3 g8(Ww/16, Hh/16, KK);
    dim3 g1(Ww/16, Hh/16, 1);

    // 1. MLP -> fm[:, 0:32] (masked)
    mlp_kernel<<<2048, 256, MLP_SMEM>>>(ray, zbufs, W1, b1, W2, b2, W3, b3, W4, b4, fm);
    // 2. sup conv1 (gather per-k colors): 3->32 relu -> t1
    conv3x3_kernel<3,3,32,true><<<g8, 256, SUP1_SMEM>>>(
        colors, k_sup1, b_sup1, t1, 0, 3*KK, 3, HWp*32, 32, 0);
    // 3. sup conv2: 32->32 -> fm[:, 32:64]
    conv3x3_kernel<32,16,32,false><<<g8, 256, SUP2_SMEM>>>(
        t1, k_sup2, b_sup2, fm, HWp*32, 32, 0, HWp*64, 64, 32);
    // 4. mpn conv1: 64->64 relu -> t2
    conv3x3_kernel<64,16,64,true><<<g8, 256, MPN_SMEM>>>(
        fm, k_mpn1, b_mpn1, t2, HWp*64, 64, 0, HWp*64, 64, 0);
    // 5. mpn conv2 + sigmoid + alpha compositing -> fuse [H,W,K]
    mpn2_fuse_kernel<<<g8, 256, MPN_SMEM>>>(k_mpn2, b_mpn2);
    // 6. unet conv1: 8->32 relu -> u1
    conv3x3_kernel<8,8,32,true><<<g1, 256, UN1_SMEM>>>(
        fuse, k_un1, b_un1, u1, 0, KK, 0, 0, 32, 0);
    // 7. unet conv2: 32->3 -> img
    unet2_kernel<<<g1, 256>>>(u1, k_un2, b_un2, (float*)d_out);
}

// round 3
// speedup vs baseline: 1.5258x; 1.5258x over previous
#include <cuda_runtime.h>
#include <cstddef>

#define Hh 512
#define Ww 512
#define KK 8
#define HWp (Hh*Ww)

typedef unsigned long long ull;

// ---------------- scratch (static device globals; no allocations) ----------------
__device__ float g_t1[KK * HWp * 32];   // sup conv1 out (relu)
__device__ float g_fm[KK * HWp * 64];   // [k][y][x][64]: feat|fc
__device__ float g_t2[KK * HWp * 64];   // mpn conv1 out (relu)
__device__ float g_fuse[HWp * KK];      // fused [y][x][k]
__device__ float g_u1[HWp * 32];        // unet conv1 out

// ---------------- packed fp32x2 helpers (Blackwell FFMA2 path) ----------------
__device__ __forceinline__ ull pack2(float v) {
    ull r; asm("mov.b64 %0, {%1, %1};" : "=l"(r) : "f"(v)); return r;
}
__device__ __forceinline__ float2 unpack2(ull v) {
    float2 f; asm("mov.b64 {%0, %1}, %2;" : "=f"(f.x), "=f"(f.y) : "l"(v)); return f;
}
__device__ __forceinline__ void fma2(ull &d, ull a, ull b) {
    asm("fma.rn.f32x2 %0, %1, %2, %0;" : "+l"(d) : "l"(a), "l"(b));
}

// =======================================================================
// Direct 3x3 SAME conv, register-blocked: thread = 4 x-pixels x 16 couts.
// Tile: 32 wide x TY tall. cout group = tid/SLOTS (warp-uniform -> weight
// LDS broadcast). Activations cached in a 6-float register window reused
// across kx taps and the 4 pixels.
// =======================================================================
template<int CIN, int CHUNK, int COUT, bool RELU>
__global__ __launch_bounds__(256, 2)
void conv3x3_kernel(const float* __restrict__ in, const float* __restrict__ wgt,
                    const float* __restrict__ bias, float* __restrict__ out,
                    int in_batch_stride, int in_pix_stride, int in_ch_per_n,
                    int out_batch_stride, int out_pix_stride, int out_ch_off)
{
    constexpr int NCG   = COUT / 16;      // cout groups
    constexpr int SLOTS = 256 / NCG;      // pixel slots (slot covers 4 x-pixels)
    constexpr int TY    = SLOTS / 8;      // tile height (tile width = 32)
    constexpr int HY    = TY + 2;
    constexpr int RS    = 37;             // halo row stride (odd -> no conflicts)
    constexpr int SIN   = ((CHUNK * HY * RS + 3) / 4) * 4;  // 16B-align weight base

    extern __shared__ float sh[];
    float* s_in = sh;                       // [CHUNK][HY][RS] (34 valid cols)
    float* s_w  = sh + SIN;                 // [9][CHUNK][COUT] (16B aligned)

    const int tid  = threadIdx.x;
    const int cg   = tid / SLOTS;
    const int slot = tid % SLOTS;
    const int sx   = (slot & 7) * 4;
    const int sy   = slot >> 3;
    const int gx = blockIdx.x * 32, gy = blockIdx.y * TY;
    const int n  = blockIdx.z;

    const float* inb = in + (size_t)n * in_batch_stride;
    const int choff_n = n * in_ch_per_n;

    ull acc[4][8];
    {
        const ull* b2 = (const ull*)(bias + cg * 16);
#pragma unroll
        for (int j = 0; j < 8; j++) {
            ull bv = __ldg(&b2[j]);
#pragma unroll
            for (int p = 0; p < 4; p++) acc[p][j] = bv;
        }
    }

    for (int c0 = 0; c0 < CIN; c0 += CHUNK) {
        // stage input halo: [c][r][j], j in [0,34)
        for (int idx = tid; idx < CHUNK * HY * 34; idx += 256) {
            int c   = idx / (HY * 34);
            int rem = idx - c * (HY * 34);
            int r   = rem / 34;
            int j   = rem - r * 34;
            int iy = gy - 1 + r, ix = gx - 1 + j;
            float v = 0.f;
            if ((unsigned)iy < Hh && (unsigned)ix < Ww)
                v = inb[(size_t)(iy * Ww + ix) * in_pix_stride + choff_n + c0 + c];
            s_in[(c * HY + r) * RS + j] = v;
        }
        // stage weights: [tap][c][cout]
        for (int idx = tid; idx < 9 * CHUNK * COUT; idx += 256) {
            int tap = idx / (CHUNK * COUT);
            int rem = idx - tap * (CHUNK * COUT);
            int c   = rem / COUT;
            int co  = rem - c * COUT;
            s_w[idx] = wgt[(size_t)(tap * CIN + c0 + c) * COUT + co];
        }
        __syncthreads();

#pragma unroll
        for (int ky = 0; ky < 3; ky++) {
#pragma unroll
            for (int c = 0; c < CHUNK; c++) {
                const float* ip = s_in + ((c * HY) + sy + ky) * RS + sx;
                float a[6];
#pragma unroll
                for (int i = 0; i < 6; i++) a[i] = ip[i];
#pragma unroll
                for (int kx = 0; kx < 3; kx++) {
                    const ulonglong2* wp = (const ulonglong2*)
                        (s_w + ((ky * 3 + kx) * CHUNK + c) * COUT + cg * 16);
                    ulonglong2 w0 = wp[0], w1 = wp[1], w2 = wp[2], w3 = wp[3];
#pragma unroll
                    for (int p = 0; p < 4; p++) {
                        ull a2 = pack2(a[kx + p]);
                        fma2(acc[p][0], a2, w0.x); fma2(acc[p][1], a2, w0.y);
                        fma2(acc[p][2], a2, w1.x); fma2(acc[p][3], a2, w1.y);
                        fma2(acc[p][4], a2, w2.x); fma2(acc[p][5], a2, w2.y);
                        fma2(acc[p][6], a2, w3.x); fma2(acc[p][7], a2, w3.y);
                    }
                }
            }
        }
        __syncthreads();
    }

#pragma unroll
    for (int p = 0; p < 4; p++) {
        float* op = out + (size_t)n * out_batch_stride
                        + (size_t)((gy + sy) * Ww + gx + sx + p) * out_pix_stride
                        + out_ch_off + cg * 16;
#pragma unroll
        for (int i = 0; i < 4; i++) {
            float2 v0 = unpack2(acc[p][2*i]), v1 = unpack2(acc[p][2*i+1]);
            float4 o = make_float4(v0.x, v0.y, v1.x, v1.y);
            if (RELU) { o.x=fmaxf(o.x,0.f); o.y=fmaxf(o.y,0.f); o.z=fmaxf(o.z,0.f); o.w=fmaxf(o.w,0.f); }
            *(float4*)(op + 4*i) = o;
        }
    }
}

// =======================================================================
// Fused MPN conv2 + sigmoid + cumprod-alpha compositing -> fuse[y][x][k]
// =======================================================================
__global__ __launch_bounds__(256, 2)
void mpn2_fuse_kernel(const float* __restrict__ wgt, const float* __restrict__ bias)
{
    constexpr int CIN = 64, CHUNK = 8, COUT = 64;
    constexpr int SLOTS = 64, TY = 8, HY = 10, RS = 37;
    constexpr int SIN = ((CHUNK * HY * RS + 3) / 4) * 4;

    extern __shared__ float sh[];
    float* s_in = sh;
    float* s_w  = sh + SIN;
    float* s_m  = sh;                      // reused after conv: [256 px][65]

    const int tid  = threadIdx.x;
    const int cg   = tid / SLOTS;
    const int slot = tid % SLOTS;
    const int sx   = (slot & 7) * 4;
    const int sy   = slot >> 3;
    const int gx = blockIdx.x * 32, gy = blockIdx.y * TY;
    const int n  = blockIdx.z;

    ull acc[4][8];
    {
        const ull* b2 = (const ull*)(bias + cg * 16);
#pragma unroll
        for (int j = 0; j < 8; j++) {
            ull bv = __ldg(&b2[j]);
#pragma unroll
            for (int p = 0; p < 4; p++) acc[p][j] = bv;
        }
    }

    for (int c0 = 0; c0 < CIN; c0 += CHUNK) {
        for (int idx = tid; idx < CHUNK * HY * 34; idx += 256) {
            int c   = idx / (HY * 34);
            int rem = idx - c * (HY * 34);
            int r   = rem / 34;
            int j   = rem - r * 34;
            int iy = gy - 1 + r, ix = gx - 1 + j;
            float v = 0.f;
            if ((unsigned)iy < Hh && (unsigned)ix < Ww)
                v = g_t2[((size_t)n * HWp + (size_t)(iy * Ww + ix)) * 64 + c0 + c];
            s_in[(c * HY + r) * RS + j] = v;
        }
        for (int idx = tid; idx < 9 * CHUNK * COUT; idx += 256) {
            int tap = idx / (CHUNK * COUT);
            int rem = idx - tap * (CHUNK * COUT);
            int c   = rem / COUT;
            int co  = rem - c * COUT;
            s_w[idx] = wgt[(size_t)(tap * CIN + c0 + c) * COUT + co];
        }
        __syncthreads();

#pragma unroll
        for (int ky = 0; ky < 3; ky++) {
#pragma unroll
            for (int c = 0; c < CHUNK; c++) {
                const float* ip = s_in + ((c * HY) + sy + ky) * RS + sx;
                float a[6];
#pragma unroll
                for (int i = 0; i < 6; i++) a[i] = ip[i];
#pragma unroll
                for (int kx = 0; kx < 3; kx++) {
                    const ulonglong2* wp = (const ulonglong2*)
                        (s_w + ((ky * 3 + kx) * CHUNK + c) * COUT + cg * 16);
                    ulonglong2 w0 = wp[0], w1 = wp[1], w2 = wp[2], w3 = wp[3];
#pragma unroll
                    for (int p = 0; p < 4; p++) {
                        ull a2 = pack2(a[kx + p]);
                        fma2(acc[p][0], a2, w0.x); fma2(acc[p][1], a2, w0.y);
                        fma2(acc[p][2], a2, w1.x); fma2(acc[p][3], a2, w1.y);
                        fma2(acc[p][4], a2, w2.x); fma2(acc[p][5], a2, w2.y);
                        fma2(acc[p][6], a2, w3.x); fma2(acc[p][7], a2, w3.y);
                    }
                }
            }
        }
        __syncthreads();
    }

    // stash logits into smem (overwrites conv staging; all reads done)
#pragma unroll
    for (int p = 0; p < 4; p++) {
        int tp = sy * 32 + sx + p;
        float* mp = s_m + tp * 65 + cg * 16;
#pragma unroll
        for (int i = 0; i < 8; i++) {
            float2 v = unpack2(acc[p][i]);
            mp[2*i] = v.x; mp[2*i+1] = v.y;
        }
    }
    __syncthreads();

    // one thread per pixel: sigmoid + cumprod composite
    {
        const int tp  = tid;
        const int py  = tp >> 5, pxl = tp & 31;
        const int pix = (gy + py) * Ww + gx + pxl;
        const float4* f4 = (const float4*)(g_fm + ((size_t)n * HWp + pix) * 64);
        const float* mp = s_m + tp * 65;
        float alpha = 1.f, fuse = 0.f;
#pragma unroll
        for (int i = 0; i < 16; i++) {
            float4 fv = __ldg(&f4[i]);
            float l0 = mp[4*i], l1 = mp[4*i+1], l2 = mp[4*i+2], l3 = mp[4*i+3];
            float m0 = 1.f / (1.f + __expf(-l0));
            fuse += fv.x * m0 * alpha; alpha *= (1.f - m0);
            float m1 = 1.f / (1.f + __expf(-l1));
            fuse += fv.y * m1 * alpha; alpha *= (1.f - m1);
            float m2 = 1.f / (1.f + __expf(-l2));
            fuse += fv.z * m2 * alpha; alpha *= (1.f - m2);
            float m3 = 1.f / (1.f + __expf(-l3));
            fuse += fv.w * m3 * alpha; alpha *= (1.f - m3);
        }
        g_fuse[(size_t)pix * KK + n] = fuse;
    }
}

// =======================================================================
// MLP kernel: warp = 16-cout group (broadcast weights), thread = 2 samples.
// =======================================================================
#define AP 133
#define OFF_W1 0
#define OFF_W2 (OFF_W1 + 3*128)
#define OFF_W3 (OFF_W2 + 128*128)
#define OFF_W4 (OFF_W3 + 131*128)
#define OFF_B1 (OFF_W4 + 128*32)
#define OFF_B2 (OFF_B1 + 128)
#define OFF_B3 (OFF_B2 + 128)
#define OFF_B4 (OFF_B3 + 128)
#define OFF_A  (OFF_B4 + 32)
#define OFF_Bb (OFF_A + 64*AP)
#define OFF_M  (OFF_Bb + 64*AP)
#define MLP_SMEM ((OFF_M + 64) * 4)

__device__ __forceinline__ void dense2(int Kin,
                                       const float* __restrict__ sA0,
                                       const float* __restrict__ sA1,
                                       const float* __restrict__ sW,
                                       const float* __restrict__ sB, int j0,
                                       float* __restrict__ o0, float* __restrict__ o1)
{
    ull a0[8], a1[8];
    const ull* bb = (const ull*)(sB + j0);
#pragma unroll
    for (int i = 0; i < 8; i++) { a0[i] = bb[i]; a1[i] = bb[i]; }
#pragma unroll 4
    for (int k = 0; k < Kin; k++) {
        ull x0 = pack2(sA0[k]);
        ull x1 = pack2(sA1[k]);
        const ulonglong2* w = (const ulonglong2*)(sW + k * 128 + j0);
        ulonglong2 w0 = w[0], w1 = w[1], w2 = w[2], w3 = w[3];
        fma2(a0[0], x0, w0.x); fma2(a0[1], x0, w0.y);
        fma2(a0[2], x0, w1.x); fma2(a0[3], x0, w1.y);
        fma2(a0[4], x0, w2.x); fma2(a0[5], x0, w2.y);
        fma2(a0[6], x0, w3.x); fma2(a0[7], x0, w3.y);
        fma2(a1[0], x1, w0.x); fma2(a1[1], x1, w0.y);
        fma2(a1[2], x1, w1.x); fma2(a1[3], x1, w1.y);
        fma2(a1[4], x1, w2.x); fma2(a1[5], x1, w2.y);
        fma2(a1[6], x1, w3.x); fma2(a1[7], x1, w3.y);
    }
#pragma unroll
    for (int i = 0; i < 8; i++) {
        float2 v0 = unpack2(a0[i]), v1 = unpack2(a1[i]);
        o0[2*i]   = fmaxf(v0.x, 0.f);
        o0[2*i+1] = fmaxf(v0.y, 0.f);
        o1[2*i]   = fmaxf(v1.x, 0.f);
        o1[2*i+1] = fmaxf(v1.y, 0.f);
    }
}

__global__ __launch_bounds__(256, 1)
void mlp_kernel(const float* __restrict__ ray, const float* __restrict__ zb,
                const float* __restrict__ W1, const float* __restrict__ b1,
                const float* __restrict__ W2, const float* __restrict__ b2,
                const float* __restrict__ W3, const float* __restrict__ b3,
                const float* __restrict__ W4, const float* __restrict__ b4,
                float* __restrict__ fm)
{
    extern __shared__ float sh[];
    const int tid = threadIdx.x;

    for (int i = tid; i < 3*128;   i += 256) sh[OFF_W1 + i] = W1[i];
    for (int i = tid; i < 128*128; i += 256) sh[OFF_W2 + i] = W2[i];
    for (int i = tid; i < 131*128; i += 256) sh[OFF_W3 + i] = W3[i];
    for (int i = tid; i < 128*32;  i += 256) sh[OFF_W4 + i] = W4[i];
    if (tid < 128) { sh[OFF_B1+tid] = b1[tid]; sh[OFF_B2+tid] = b2[tid]; sh[OFF_B3+tid] = b3[tid]; }
    if (tid < 32)  sh[OFF_B4 + tid] = b4[tid];
    __syncthreads();

    const int lane = tid & 31;
    const int warp = tid >> 5;       // 0..7 -> cout group of 16
    const int j0   = warp * 16;
    const int sA   = lane;
    const int sB_  = lane + 32;
    const int NTILE = (KK * HWp) / 64;

    for (int tile = blockIdx.x; tile < NTILE; tile += gridDim.x) {
        if (tid < 64) {
            int sid = tile * 64 + tid;
            int kk  = sid / HWp;
            int pix = sid - kk * HWp;
            const float* r = ray + (size_t)pix * 7;
            float z = zb[(size_t)pix * KK + kk];
            float t = z / r[6];
            float* Ar = sh + OFF_A + tid * AP;
            Ar[0] = r[0] + r[3] * t;
            Ar[1] = r[1] + r[4] * t;
            Ar[2] = r[2] + r[5] * t;
            Ar[128] = r[3]; Ar[129] = r[4]; Ar[130] = r[5];
            sh[OFF_M + tid] = (z > 0.f) ? 1.f : 0.f;
        }
        __syncthreads();
        dense2(3, sh + OFF_A + sA*AP, sh + OFF_A + sB_*AP,
               sh + OFF_W1, sh + OFF_B1, j0,
               sh + OFF_Bb + sA*AP + j0, sh + OFF_Bb + sB_*AP + j0);
        __syncthreads();
        dense2(128, sh + OFF_Bb + sA*AP, sh + OFF_Bb + sB_*AP,
               sh + OFF_W2, sh + OFF_B2, j0,
               sh + OFF_A + sA*AP + j0, sh + OFF_A + sB_*AP + j0);
        __syncthreads();
        dense2(131, sh + OFF_A + sA*AP, sh + OFF_A + sB_*AP,
               sh + OFF_W3, sh + OFF_B3, j0,
               sh + OFF_Bb + sA*AP + j0, sh + OFF_Bb + sB_*AP + j0);
        __syncthreads();
        // layer4: 32 couts over 8 warps -> 4 couts each
        {
            const int j4 = warp * 4;
            ull a0[2], a1[2];
            const ull* bb = (const ull*)(sh + OFF_B4 + j4);
            a0[0] = bb[0]; a0[1] = bb[1];
            a1[0] = bb[0]; a1[1] = bb[1];
            const float* in0 = sh + OFF_Bb + sA*AP;
            const float* in1 = sh + OFF_Bb + sB_*AP;
#pragma unroll 4
            for (int k = 0; k < 128; k++) {
                ull x0 = pack2(in0[k]);
                ull x1 = pack2(in1[k]);
                const ull* w = (const ull*)(sh + OFF_W4 + k * 32 + j4);
                ull w0 = w[0], w1 = w[1];
                fma2(a0[0], x0, w0); fma2(a0[1], x0, w1);
                fma2(a1[0], x1, w0); fma2(a1[1], x1, w1);
            }
            float mf0 = sh[OFF_M + sA];
            float mf1 = sh[OFF_M + sB_];
            size_t sid0 = (size_t)tile * 64 + sA;
            size_t sid1 = (size_t)tile * 64 + sB_;
            float2 v0 = unpack2(a0[0]), v1 = unpack2(a0[1]);
            *(float4*)(fm + sid0 * 64 + j4) = make_float4(v0.x*mf0, v0.y*mf0, v1.x*mf0, v1.y*mf0);
            float2 u0 = unpack2(a1[0]), u1 = unpack2(a1[1]);
            *(float4*)(fm + sid1 * 64 + j4) = make_float4(u0.x*mf1, u0.y*mf1, u1.x*mf1, u1.y*mf1);
        }
        __syncthreads();
    }
}

// =======================================================================
// unet conv2: 32 -> 3 (no relu) -> final image
// =======================================================================
__global__ __launch_bounds__(256)
void unet2_kernel(const float* __restrict__ in, const float* __restrict__ wgt,
                  const float* __restrict__ bias, float* __restrict__ out)
{
    constexpr int CIN = 32, CHUNK = 16, SP = CHUNK + 1;
    __shared__ float s_in[324 * SP];
    __shared__ float s_w[9 * CHUNK * 3];

    const int tid = threadIdx.x;
    const int tx = tid & 15, ty = tid >> 4;
    const int gx = blockIdx.x * 16, gy = blockIdx.y * 16;

    float acc0 = __ldg(&bias[0]), acc1 = __ldg(&bias[1]), acc2 = __ldg(&bias[2]);

    for (int c0 = 0; c0 < CIN; c0 += CHUNK) {
        for (int idx = tid; idx < 324 * CHUNK; idx += 256) {
            int p = idx / CHUNK, c = idx - p * CHUNK;
            int py = p / 18, px = p - py * 18;
            int iy = gy - 1 + py, ix = gx - 1 + px;
            float v = 0.f;
            if ((unsigned)iy < Hh && (unsigned)ix < Ww)
                v = in[(size_t)(iy * Ww + ix) * CIN + c0 + c];
            s_in[p * SP + c] = v;
        }
        for (int idx = tid; idx < 9 * CHUNK * 3; idx += 256) {
            int tap = idx / (CHUNK * 3);
            int r   = idx - tap * (CHUNK * 3);
            int c   = r / 3, co = r - c * 3;
            s_w[idx] = wgt[(size_t)(tap * CIN + c0 + c) * 3 + co];
        }
        __syncthreads();
#pragma unroll
        for (int tap = 0; tap < 9; tap++) {
            int ky = tap / 3, kx = tap - ky * 3;
            const float* ip = s_in + ((ty + ky) * 18 + tx + kx) * SP;
            const float* wp = s_w + tap * CHUNK * 3;
#pragma unroll
            for (int c = 0; c < CHUNK; c++) {
                float a = ip[c];
                acc0 += a * wp[c*3 + 0];
                acc1 += a * wp[c*3 + 1];
                acc2 += a * wp[c*3 + 2];
            }
        }
        __syncthreads();
    }
    float* op = out + (size_t)((gy + ty) * Ww + gx + tx) * 3;
    op[0] = acc0; op[1] = acc1; op[2] = acc2;
}

// =======================================================================
extern "C" void kernel_launch(void* const* d_in, const int* in_sizes, int n_in,
                              void* d_out, int out_size)
{
    const float* colors = (const float*)d_in[0];
    const float* ray    = (const float*)d_in[1];
    const float* zbufs  = (const float*)d_in[2];
    const float* W1 = (const float*)d_in[3];  const float* b1 = (const float*)d_in[4];
    const float* W2 = (const float*)d_in[5];  const float* b2 = (const float*)d_in[6];
    const float* W3 = (const float*)d_in[7];  const float* b3 = (const float*)d_in[8];
    const float* W4 = (const float*)d_in[9];  const float* b4 = (const float*)d_in[10];
    const float* k_sup1 = (const float*)d_in[11]; const float* b_sup1 = (const float*)d_in[12];
    const float* k_sup2 = (const float*)d_in[13]; const float* b_sup2 = (const float*)d_in[14];
    const float* k_mpn1 = (const float*)d_in[15]; const float* b_mpn1 = (const float*)d_in[16];
    const float* k_mpn2 = (const float*)d_in[17]; const float* b_mpn2 = (const float*)d_in[18];
    const float* k_un1  = (const float*)d_in[19]; const float* b_un1  = (const float*)d_in[20];
    const float* k_un2  = (const float*)d_in[21]; const float* b_un2  = (const float*)d_in[22];

    float *t1, *fm, *t2, *fuse, *u1;
    cudaGetSymbolAddress((void**)&t1,   g_t1);
    cudaGetSymbolAddress((void**)&fm,   g_fm);
    cudaGetSymbolAddress((void**)&t2,   g_t2);
    cudaGetSymbolAddress((void**)&fuse, g_fuse);
    cudaGetSymbolAddress((void**)&u1,   g_u1);

    // dynamic smem sizes (align4 on the halo region, matching SIN in-kernel)
    auto A4 = [](int x){ return ((x + 3) / 4) * 4; };
    const int SUP1_SMEM = (A4(3*18*37) + 9*3*32) * 4;
    const int SUP2_SMEM = (A4(8*18*37) + 9*8*32) * 4;
    const int MPN1_SMEM = (A4(8*10*37) + 9*8*64) * 4;
    int mpn2_conv = (A4(8*10*37) + 9*8*64) * 4;
    int mpn2_epi  = 256 * 65 * 4;
    const int MPN2_SMEM = mpn2_conv > mpn2_epi ? mpn2_conv : mpn2_epi;
    const int UN1_SMEM  = (A4(8*18*37) + 9*8*32) * 4;

    cudaFuncSetAttribute(mlp_kernel, cudaFuncAttributeMaxDynamicSharedMemorySize, MLP_SMEM);
    cudaFuncSetAttribute(mpn2_fuse_kernel, cudaFuncAttributeMaxDynamicSharedMemorySize, MPN2_SMEM);

    // 1. MLP -> fm[:, 0:32] (masked)
    mlp_kernel<<<2048, 256, MLP_SMEM>>>(ray, zbufs, W1, b1, W2, b2, W3, b3, W4, b4, fm);
    // 2. sup conv1 (gather per-k colors): 3->32 relu -> t1   (COUT=32 -> TY=16)
    conv3x3_kernel<3,3,32,true><<<dim3(16,32,8), 256, SUP1_SMEM>>>(
        colors, k_sup1, b_sup1, t1, 0, 3*KK, 3, HWp*32, 32, 0);
    // 3. sup conv2: 32->32 -> fm[:, 32:64]
    conv3x3_kernel<32,8,32,false><<<dim3(16,32,8), 256, SUP2_SMEM>>>(
        t1, k_sup2, b_sup2, fm, HWp*32, 32, 0, HWp*64, 64, 32);
    // 4. mpn conv1: 64->64 relu -> t2   (COUT=64 -> TY=8)
    conv3x3_kernel<64,8,64,true><<<dim3(16,64,8), 256, MPN1_SMEM>>>(
        fm, k_mpn1, b_mpn1, t2, HWp*64, 64, 0, HWp*64, 64, 0);
    // 5. mpn conv2 + sigmoid + alpha compositing -> fuse [H,W,K]
    mpn2_fuse_kernel<<<dim3(16,64,8), 256, MPN2_SMEM>>>(k_mpn2, b_mpn2);
    // 6. unet conv1: 8->32 relu -> u1
    conv3x3_kernel<8,8,32,true><<<dim3(16,32,1), 256, UN1_SMEM>>>(
        fuse, k_un1, b_un1, u1, 0, KK, 0, 0, 32, 0);
    // 7. unet conv2: 32->3 -> img
    unet2_kernel<<<dim3(32,32,1), 256>>>(u1, k_un2, b_un2, (float*)d_out);
}

// round 6
// speedup vs baseline: 1.9837x; 1.3001x over previous
#include <cuda_runtime.h>
#include <cstddef>
#include <cstdint>

#define Hh 512
#define Ww 512
#define KK 8
#define HWp (Hh*Ww)

typedef unsigned long long ull;

__device__ float g_t1[KK * HWp * 32];
__device__ float g_fm[KK * HWp * 64];
__device__ float g_t2[KK * HWp * 64];
__device__ float g_fuse[HWp * KK];
__device__ float g_u1[HWp * 32];
__device__ float g_wB[2 * 36864];   // prepped MPN weights (tf32 bits)

// ---------------- packed fp32x2 helpers ----------------
__device__ __forceinline__ ull pack2(float v) {
    ull r; asm("mov.b64 %0, {%1, %1};" : "=l"(r) : "f"(v)); return r;
}
__device__ __forceinline__ float2 unpack2(ull v) {
    float2 f; asm("mov.b64 {%0, %1}, %2;" : "=f"(f.x), "=f"(f.y) : "l"(v)); return f;
}
__device__ __forceinline__ void fma2(ull &d, ull a, ull b) {
    asm("fma.rn.f32x2 %0, %1, %2, %0;" : "+l"(d) : "l"(a), "l"(b));
}

// ---------------- warp mma tf32 m16n8k8 ----------------
__device__ __forceinline__ void mma_tf32(float* c,
                                         float a0, float a1, float a2, float a3,
                                         float b0, float b1)
{
    asm volatile(
        "mma.sync.aligned.m16n8k8.row.col.f32.tf32.tf32.f32 "
        "{%0,%1,%2,%3}, {%4,%5,%6,%7}, {%8,%9}, {%0,%1,%2,%3};"
        : "+f"(c[0]), "+f"(c[1]), "+f"(c[2]), "+f"(c[3])
        : "r"(__float_as_uint(a0)), "r"(__float_as_uint(a1)),
          "r"(__float_as_uint(a2)), "r"(__float_as_uint(a3)),
          "r"(__float_as_uint(b0)), "r"(__float_as_uint(b1)));
}

// =======================================================================
// Weight prep: k_mpn HWIO [tap][cin][cout] -> s_w layout
//   [h][tap][g][co 0..63][c 0..3][s 0..1], cin = h*32 + g*8 + c + s*4
// with cvt.rna.tf32 applied once.
// =======================================================================
__global__ void wprep_kernel(const float* __restrict__ w1, const float* __restrict__ w2)
{
    int i = blockIdx.x * 256 + threadIdx.x;
    if (i >= 36864) return;
    int s   = i & 1;
    int c   = (i >> 1) & 3;
    int co  = (i >> 3) & 63;
    int blk = i >> 9;            // (h*9+tap)*4+g
    int g   = blk & 3;
    int ht  = blk >> 2;          // h*9+tap
    int h   = ht / 9, tap = ht - h * 9;
    int cin = h * 32 + g * 8 + c + s * 4;
    int src = (tap * 64 + cin) * 64 + co;
    uint32_t o1, o2;
    asm("cvt.rna.tf32.f32 %0, %1;" : "=r"(o1) : "f"(w1[src]));
    asm("cvt.rna.tf32.f32 %0, %1;" : "=r"(o2) : "f"(w2[src]));
    g_wB[i]         = __uint_as_float(o1);
    g_wB[36864 + i] = __uint_as_float(o2);
}

// =======================================================================
// MPN conv 64->64 via mma.sync tf32.
// CTA: 128-px x-strip, one y row; 8 warps; warp = 16 px x 64 couts.
// SMEM floats: bias[64] | s_w[36864] | s_a[3*130*40] (reused as logits)
// A smem: [ky][px][g][c][s] pairs (ci, ci+4), px stride 40.
// =======================================================================
#define WST 40
#define SW_OFF 64
#define SA_OFF (64 + 36864)
#define MPN_SMEM_BYTES ((SA_OFF + 3*130*WST) * 4)   // 210112

template<bool FUSE>
__global__ __launch_bounds__(256, 1)
void mpn_mma_kernel(const float* __restrict__ in, const float* __restrict__ wB,
                    const float* __restrict__ bias,
                    float* __restrict__ out, const float* __restrict__ fmc)
{
    extern __shared__ float sh[];
    float* s_bias = sh;
    float* s_w    = sh + SW_OFF;
    float* s_a    = sh + SA_OFF;
    float* s_l    = s_a;               // logits reuse (FUSE)

    const int tid  = threadIdx.x;
    const int wrp  = tid >> 5, lane = tid & 31;
    const int r    = lane >> 2, cq = lane & 3;
    const int gx   = blockIdx.x * 128;
    const int y    = blockIdx.y;

    {   // stage weights + bias
        const float4* src = (const float4*)wB;
        float4* dst = (float4*)s_w;
        for (int i = tid; i < 9216; i += 256) dst[i] = src[i];
        if (tid < 64) s_bias[tid] = bias[tid];
    }
    __syncthreads();

    float bia[8][2];
#pragma unroll
    for (int cg = 0; cg < 8; cg++) {
        bia[cg][0] = s_bias[cg * 8 + cq * 2];
        bia[cg][1] = s_bias[cg * 8 + cq * 2 + 1];
    }

    for (int k = 0; k < KK; k++) {
        float c[8][4];
#pragma unroll
        for (int cg = 0; cg < 8; cg++) {
            c[cg][0] = bia[cg][0]; c[cg][1] = bia[cg][1];
            c[cg][2] = bia[cg][0]; c[cg][3] = bia[cg][1];
        }
#pragma unroll 1
        for (int h = 0; h < 2; h++) {
            // stage A half: 3 planes x 130 px x 32 cin, (ci,ci+4) interleave
            const float* inb = in + ((size_t)k * HWp) * 64 + h * 32;
            for (int it = tid; it < 1560; it += 256) {
                int ky  = it / 520;
                int rem = it - ky * 520;
                int p   = rem >> 2, g = rem & 3;
                int iy = y + ky - 1, ix = gx + p - 1;
                float4 lo = make_float4(0.f,0.f,0.f,0.f);
                float4 hi = make_float4(0.f,0.f,0.f,0.f);
                if ((unsigned)iy < Hh && (unsigned)ix < Ww) {
                    const float* q = inb + ((size_t)iy * Ww + ix) * 64 + g * 8;
                    lo = *(const float4*)q;
                    hi = *(const float4*)(q + 4);
                }
                float* d = s_a + (ky * 130 + p) * WST + g * 8;
                d[0] = lo.x; d[1] = hi.x; d[2] = lo.y; d[3] = hi.y;
                d[4] = lo.z; d[5] = hi.z; d[6] = lo.w; d[7] = hi.w;
            }
            __syncthreads();
#pragma unroll
            for (int tap = 0; tap < 9; tap++) {
                const int ky = tap / 3, kx = tap - ky * 3;
#pragma unroll
                for (int g = 0; g < 4; g++) {
                    const float* ap = s_a + (ky * 130 + kx + wrp * 16 + r) * WST + g * 8 + cq * 2;
                    float a0 = ap[0],         a2 = ap[1];
                    float a1 = ap[8 * WST],   a3 = ap[8 * WST + 1];
                    const float* wp = s_w + (((h * 9 + tap) * 4 + g) << 9) + r * 8 + cq * 2;
#pragma unroll
                    for (int cg = 0; cg < 8; cg++) {
                        float b0 = wp[cg * 64], b1 = wp[cg * 64 + 1];
                        mma_tf32(c[cg], a0, a1, a2, a3, b0, b1);
                    }
                }
            }
            __syncthreads();
        }

        if (!FUSE) {
            // bias already in C; relu; direct store from fragments
            const size_t pixbase = (size_t)k * HWp + (size_t)y * Ww + gx + wrp * 16;
            float* o0 = out + (pixbase + r) * 64;
            float* o1 = out + (pixbase + r + 8) * 64;
#pragma unroll
            for (int cg = 0; cg < 8; cg++) {
                float2 v0 = make_float2(fmaxf(c[cg][0], 0.f), fmaxf(c[cg][1], 0.f));
                float2 v1 = make_float2(fmaxf(c[cg][2], 0.f), fmaxf(c[cg][3], 0.f));
                *(float2*)(o0 + cg * 8 + cq * 2) = v0;
                *(float2*)(o1 + cg * 8 + cq * 2) = v1;
            }
        } else {
            // dump logits to smem [px][65], then per-pixel composite
            const int p0 = wrp * 16 + r;
#pragma unroll
            for (int cg = 0; cg < 8; cg++) {
                float* l0 = s_l + p0 * 65 + cg * 8 + cq * 2;
                l0[0] = c[cg][0]; l0[1] = c[cg][1];
                float* l1 = s_l + (p0 + 8) * 65 + cg * 8 + cq * 2;
                l1[0] = c[cg][2]; l1[1] = c[cg][3];
            }
            __syncthreads();
            if (tid < 128) {
                const int px = tid;
                const size_t pix = (size_t)y * Ww + gx + px;
                const float4* f4 = (const float4*)(fmc + ((size_t)k * HWp + pix) * 64);
                const float* lp = s_l + px * 65;
                float alpha = 1.f, fs = 0.f;
#pragma unroll
                for (int i = 0; i < 16; i++) {
                    float4 fv = __ldg(&f4[i]);
                    float l0 = lp[4*i], l1 = lp[4*i+1], l2 = lp[4*i+2], l3 = lp[4*i+3];
                    float m0 = 1.f / (1.f + __expf(-l0));
                    fs += fv.x * m0 * alpha; alpha *= (1.f - m0);
                    float m1 = 1.f / (1.f + __expf(-l1));
                    fs += fv.y * m1 * alpha; alpha *= (1.f - m1);
                    float m2 = 1.f / (1.f + __expf(-l2));
                    fs += fv.z * m2 * alpha; alpha *= (1.f - m2);
                    float m3 = 1.f / (1.f + __expf(-l3));
                    fs += fv.w * m3 * alpha; alpha *= (1.f - m3);
                }
                out[pix * KK + k] = fs;
            }
            __syncthreads();
        }
    }
}

// =======================================================================
// Direct 3x3 conv (fp32 FFMA2) — sup1/sup2/un1 (unchanged R3)
// =======================================================================
template<int CIN, int CHUNK, int COUT, bool RELU>
__global__ __launch_bounds__(256, 2)
void conv3x3_kernel(const float* __restrict__ in, const float* __restrict__ wgt,
                    const float* __restrict__ bias, float* __restrict__ out,
                    int in_batch_stride, int in_pix_stride, int in_ch_per_n,
                    int out_batch_stride, int out_pix_stride, int out_ch_off)
{
    constexpr int NCG   = COUT / 16;
    constexpr int SLOTS = 256 / NCG;
    constexpr int TY    = SLOTS / 8;
    constexpr int HY    = TY + 2;
    constexpr int RS    = 37;
    constexpr int SIN   = ((CHUNK * HY * RS + 3) / 4) * 4;

    extern __shared__ float sh[];
    float* s_in = sh;
    float* s_w  = sh + SIN;

    const int tid  = threadIdx.x;
    const int cg   = tid / SLOTS;
    const int slot = tid % SLOTS;
    const int sx   = (slot & 7) * 4;
    const int sy   = slot >> 3;
    const int gx = blockIdx.x * 32, gy = blockIdx.y * TY;
    const int n  = blockIdx.z;

    const float* inb = in + (size_t)n * in_batch_stride;
    const int choff_n = n * in_ch_per_n;

    ull acc[4][8];
    {
        const ull* b2 = (const ull*)(bias + cg * 16);
#pragma unroll
        for (int j = 0; j < 8; j++) {
            ull bv = __ldg(&b2[j]);
#pragma unroll
            for (int p = 0; p < 4; p++) acc[p][j] = bv;
        }
    }
    for (int c0 = 0; c0 < CIN; c0 += CHUNK) {
        for (int idx = tid; idx < CHUNK * HY * 34; idx += 256) {
            int c   = idx / (HY * 34);
            int rem = idx - c * (HY * 34);
            int rr  = rem / 34;
            int j   = rem - rr * 34;
            int iy = gy - 1 + rr, ix = gx - 1 + j;
            float v = 0.f;
            if ((unsigned)iy < Hh && (unsigned)ix < Ww)
                v = inb[(size_t)(iy * Ww + ix) * in_pix_stride + choff_n + c0 + c];
            s_in[(c * HY + rr) * RS + j] = v;
        }
        for (int idx = tid; idx < 9 * CHUNK * COUT; idx += 256) {
            int tap = idx / (CHUNK * COUT);
            int rem = idx - tap * (CHUNK * COUT);
            int c   = rem / COUT;
            int co  = rem - c * COUT;
            s_w[idx] = wgt[(size_t)(tap * CIN + c0 + c) * COUT + co];
        }
        __syncthreads();
#pragma unroll
        for (int ky = 0; ky < 3; ky++) {
#pragma unroll
            for (int c = 0; c < CHUNK; c++) {
                const float* ip = s_in + ((c * HY) + sy + ky) * RS + sx;
                float a[6];
#pragma unroll
                for (int i = 0; i < 6; i++) a[i] = ip[i];
#pragma unroll
                for (int kx = 0; kx < 3; kx++) {
                    const ulonglong2* wp = (const ulonglong2*)
                        (s_w + ((ky * 3 + kx) * CHUNK + c) * COUT + cg * 16);
                    ulonglong2 w0 = wp[0], w1 = wp[1], w2 = wp[2], w3 = wp[3];
#pragma unroll
                    for (int p = 0; p < 4; p++) {
                        ull a2 = pack2(a[kx + p]);
                        fma2(acc[p][0], a2, w0.x); fma2(acc[p][1], a2, w0.y);
                        fma2(acc[p][2], a2, w1.x); fma2(acc[p][3], a2, w1.y);
                        fma2(acc[p][4], a2, w2.x); fma2(acc[p][5], a2, w2.y);
                        fma2(acc[p][6], a2, w3.x); fma2(acc[p][7], a2, w3.y);
                    }
                }
            }
        }
        __syncthreads();
    }
#pragma unroll
    for (int p = 0; p < 4; p++) {
        float* op = out + (size_t)n * out_batch_stride
                        + (size_t)((gy + sy) * Ww + gx + sx + p) * out_pix_stride
                        + out_ch_off + cg * 16;
#pragma unroll
        for (int i = 0; i < 4; i++) {
            float2 v0 = unpack2(acc[p][2*i]), v1 = unpack2(acc[p][2*i+1]);
            float4 o = make_float4(v0.x, v0.y, v1.x, v1.y);
            if (RELU) { o.x=fmaxf(o.x,0.f); o.y=fmaxf(o.y,0.f); o.z=fmaxf(o.z,0.f); o.w=fmaxf(o.w,0.f); }
            *(float4*)(op + 4*i) = o;
        }
    }
}

// =======================================================================
// MLP kernel (unchanged R3)
// =======================================================================
#define AP 133
#define OFF_W1 0
#define OFF_W2 (OFF_W1 + 3*128)
#define OFF_W3 (OFF_W2 + 128*128)
#define OFF_W4 (OFF_W3 + 131*128)
#define OFF_B1 (OFF_W4 + 128*32)
#define OFF_B2 (OFF_B1 + 128)
#define OFF_B3 (OFF_B2 + 128)
#define OFF_B4 (OFF_B3 + 128)
#define OFF_A  (OFF_B4 + 32)
#define OFF_Bb (OFF_A + 64*AP)
#define OFF_M  (OFF_Bb + 64*AP)
#define MLP_SMEM ((OFF_M + 64) * 4)

__device__ __forceinline__ void dense2(int Kin,
                                       const float* __restrict__ sA0,
                                       const float* __restrict__ sA1,
                                       const float* __restrict__ sW,
                                       const float* __restrict__ sB, int j0,
                                       float* __restrict__ o0, float* __restrict__ o1)
{
    ull a0[8], a1[8];
    const ull* bb = (const ull*)(sB + j0);
#pragma unroll
    for (int i = 0; i < 8; i++) { a0[i] = bb[i]; a1[i] = bb[i]; }
#pragma unroll 4
    for (int k = 0; k < Kin; k++) {
        ull x0 = pack2(sA0[k]);
        ull x1 = pack2(sA1[k]);
        const ulonglong2* w = (const ulonglong2*)(sW + k * 128 + j0);
        ulonglong2 w0 = w[0], w1 = w[1], w2 = w[2], w3 = w[3];
        fma2(a0[0], x0, w0.x); fma2(a0[1], x0, w0.y);
        fma2(a0[2], x0, w1.x); fma2(a0[3], x0, w1.y);
        fma2(a0[4], x0, w2.x); fma2(a0[5], x0, w2.y);
        fma2(a0[6], x0, w3.x); fma2(a0[7], x0, w3.y);
        fma2(a1[0], x1, w0.x); fma2(a1[1], x1, w0.y);
        fma2(a1[2], x1, w1.x); fma2(a1[3], x1, w1.y);
        fma2(a1[4], x1, w2.x); fma2(a1[5], x1, w2.y);
        fma2(a1[6], x1, w3.x); fma2(a1[7], x1, w3.y);
    }
#pragma unroll
    for (int i = 0; i < 8; i++) {
        float2 v0 = unpack2(a0[i]), v1 = unpack2(a1[i]);
        o0[2*i]   = fmaxf(v0.x, 0.f);
        o0[2*i+1] = fmaxf(v0.y, 0.f);
        o1[2*i]   = fmaxf(v1.x, 0.f);
        o1[2*i+1] = fmaxf(v1.y, 0.f);
    }
}

__global__ __launch_bounds__(256, 1)
void mlp_kernel(const float* __restrict__ ray, const float* __restrict__ zb,
                const float* __restrict__ W1, const float* __restrict__ b1,
                const float* __restrict__ W2, const float* __restrict__ b2,
                const float* __restrict__ W3, const float* __restrict__ b3,
                const float* __restrict__ W4, const float* __restrict__ b4,
                float* __restrict__ fm)
{
    extern __shared__ float sh[];
    const int tid = threadIdx.x;
    for (int i = tid; i < 3*128;   i += 256) sh[OFF_W1 + i] = W1[i];
    for (int i = tid; i < 128*128; i += 256) sh[OFF_W2 + i] = W2[i];
    for (int i = tid; i < 131*128; i += 256) sh[OFF_W3 + i] = W3[i];
    for (int i = tid; i < 128*32;  i += 256) sh[OFF_W4 + i] = W4[i];
    if (tid < 128) { sh[OFF_B1+tid] = b1[tid]; sh[OFF_B2+tid] = b2[tid]; sh[OFF_B3+tid] = b3[tid]; }
    if (tid < 32)  sh[OFF_B4 + tid] = b4[tid];
    __syncthreads();

    const int lane = tid & 31;
    const int warp = tid >> 5;
    const int j0   = warp * 16;
    const int sA   = lane;
    const int sB_  = lane + 32;
    const int NTILE = (KK * HWp) / 64;

    for (int tile = blockIdx.x; tile < NTILE; tile += gridDim.x) {
        if (tid < 64) {
            int sid = tile * 64 + tid;
            int kk  = sid / HWp;
            int pix = sid - kk * HWp;
            const float* r = ray + (size_t)pix * 7;
            float z = zb[(size_t)pix * KK + kk];
            float t = z / r[6];
            float* Ar = sh + OFF_A + tid * AP;
            Ar[0] = r[0] + r[3] * t;
            Ar[1] = r[1] + r[4] * t;
            Ar[2] = r[2] + r[5] * t;
            Ar[128] = r[3]; Ar[129] = r[4]; Ar[130] = r[5];
            sh[OFF_M + tid] = (z > 0.f) ? 1.f : 0.f;
        }
        __syncthreads();
        dense2(3, sh + OFF_A + sA*AP, sh + OFF_A + sB_*AP,
               sh + OFF_W1, sh + OFF_B1, j0,
               sh + OFF_Bb + sA*AP + j0, sh + OFF_Bb + sB_*AP + j0);
        __syncthreads();
        dense2(128, sh + OFF_Bb + sA*AP, sh + OFF_Bb + sB_*AP,
               sh + OFF_W2, sh + OFF_B2, j0,
               sh + OFF_A + sA*AP + j0, sh + OFF_A + sB_*AP + j0);
        __syncthreads();
        dense2(131, sh + OFF_A + sA*AP, sh + OFF_A + sB_*AP,
               sh + OFF_W3, sh + OFF_B3, j0,
               sh + OFF_Bb + sA*AP + j0, sh + OFF_Bb + sB_*AP + j0);
        __syncthreads();
        {
            const int j4 = warp * 4;
            ull a0[2], a1[2];
            const ull* bb = (const ull*)(sh + OFF_B4 + j4);
            a0[0] = bb[0]; a0[1] = bb[1];
            a1[0] = bb[0]; a1[1] = bb[1];
            const float* in0 = sh + OFF_Bb + sA*AP;
            const float* in1 = sh + OFF_Bb + sB_*AP;
#pragma unroll 4
            for (int k = 0; k < 128; k++) {
                ull x0 = pack2(in0[k]);
                ull x1 = pack2(in1[k]);
                const ull* w = (const ull*)(sh + OFF_W4 + k * 32 + j4);
                ull w0 = w[0], w1 = w[1];
                fma2(a0[0], x0, w0); fma2(a0[1], x0, w1);
                fma2(a1[0], x1, w0); fma2(a1[1], x1, w1);
            }
            float mf0 = sh[OFF_M + sA];
            float mf1 = sh[OFF_M + sB_];
            size_t sid0 = (size_t)tile * 64 + sA;
            size_t sid1 = (size_t)tile * 64 + sB_;
            float2 v0 = unpack2(a0[0]), v1 = unpack2(a0[1]);
            *(float4*)(fm + sid0 * 64 + j4) = make_float4(v0.x*mf0, v0.y*mf0, v1.x*mf0, v1.y*mf0);
            float2 u0 = unpack2(a1[0]), u1 = unpack2(a1[1]);
            *(float4*)(fm + sid1 * 64 + j4) = make_float4(u0.x*mf1, u0.y*mf1, u1.x*mf1, u1.y*mf1);
        }
        __syncthreads();
    }
}

// =======================================================================
// unet conv2: 32 -> 3 (unchanged R3)
// =======================================================================
__global__ __launch_bounds__(256)
void unet2_kernel(const float* __restrict__ in, const float* __restrict__ wgt,
                  const float* __restrict__ bias, float* __restrict__ out)
{
    constexpr int CIN = 32, CHUNK = 16, SP = CHUNK + 1;
    __shared__ float s_in[324 * SP];
    __shared__ float s_w[9 * CHUNK * 3];

    const int tid = threadIdx.x;
    const int tx = tid & 15, ty = tid >> 4;
    const int gx = blockIdx.x * 16, gy = blockIdx.y * 16;

    float acc0 = __ldg(&bias[0]), acc1 = __ldg(&bias[1]), acc2 = __ldg(&bias[2]);

    for (int c0 = 0; c0 < CIN; c0 += CHUNK) {
        for (int idx = tid; idx < 324 * CHUNK; idx += 256) {
            int p = idx / CHUNK, c = idx - p * CHUNK;
            int py = p / 18, px = p - py * 18;
            int iy = gy - 1 + py, ix = gx - 1 + px;
            float v = 0.f;
            if ((unsigned)iy < Hh && (unsigned)ix < Ww)
                v = in[(size_t)(iy * Ww + ix) * CIN + c0 + c];
            s_in[p * SP + c] = v;
        }
        for (int idx = tid; idx < 9 * CHUNK * 3; idx += 256) {
            int tap = idx / (CHUNK * 3);
            int r   = idx - tap * (CHUNK * 3);
            int c   = r / 3, co = r - c * 3;
            s_w[idx] = wgt[(size_t)(tap * CIN + c0 + c) * 3 + co];
        }
        __syncthreads();
#pragma unroll
        for (int tap = 0; tap < 9; tap++) {
            int ky = tap / 3, kx = tap - ky * 3;
            const float* ip = s_in + ((ty + ky) * 18 + tx + kx) * SP;
            const float* wp = s_w + tap * CHUNK * 3;
#pragma unroll
            for (int c = 0; c < CHUNK; c++) {
                float a = ip[c];
                acc0 += a * wp[c*3 + 0];
                acc1 += a * wp[c*3 + 1];
                acc2 += a * wp[c*3 + 2];
            }
        }
        __syncthreads();
    }
    float* op = out + (size_t)((gy + ty) * Ww + gx + tx) * 3;
    op[0] = acc0; op[1] = acc1; op[2] = acc2;
}

// =======================================================================
extern "C" void kernel_launch(void* const* d_in, const int* in_sizes, int n_in,
                              void* d_out, int out_size)
{
    const float* colors = (const float*)d_in[0];
    const float* ray    = (const float*)d_in[1];
    const float* zbufs  = (const float*)d_in[2];
    const float* W1 = (const float*)d_in[3];  const float* b1 = (const float*)d_in[4];
    const float* W2 = (const float*)d_in[5];  const float* b2 = (const float*)d_in[6];
    const float* W3 = (const float*)d_in[7];  const float* b3 = (const float*)d_in[8];
    const float* W4 = (const float*)d_in[9];  const float* b4 = (const float*)d_in[10];
    const float* k_sup1 = (const float*)d_in[11]; const float* b_sup1 = (const float*)d_in[12];
    const float* k_sup2 = (const float*)d_in[13]; const float* b_sup2 = (const float*)d_in[14];
    const float* k_mpn1 = (const float*)d_in[15]; const float* b_mpn1 = (const float*)d_in[16];
    const float* k_mpn2 = (const float*)d_in[17]; const float* b_mpn2 = (const float*)d_in[18];
    const float* k_un1  = (const float*)d_in[19]; const float* b_un1  = (const float*)d_in[20];
    const float* k_un2  = (const float*)d_in[21]; const float* b_un2  = (const float*)d_in[22];

    float *t1, *fm, *t2, *fuse, *u1, *wB;
    cudaGetSymbolAddress((void**)&t1,   g_t1);
    cudaGetSymbolAddress((void**)&fm,   g_fm);
    cudaGetSymbolAddress((void**)&t2,   g_t2);
    cudaGetSymbolAddress((void**)&fuse, g_fuse);
    cudaGetSymbolAddress((void**)&u1,   g_u1);
    cudaGetSymbolAddress((void**)&wB,   g_wB);

    auto A4 = [](int x){ return ((x + 3) / 4) * 4; };
    const int SUP1_SMEM = (A4(3*18*37) + 9*3*32) * 4;
    const int SUP2_SMEM = (A4(8*18*37) + 9*8*32) * 4;
    const int UN1_SMEM  = (A4(8*18*37) + 9*8*32) * 4;

    cudaFuncSetAttribute(mlp_kernel, cudaFuncAttributeMaxDynamicSharedMemorySize, MLP_SMEM);
    cudaFuncSetAttribute(mpn_mma_kernel<false>, cudaFuncAttributeMaxDynamicSharedMemorySize, MPN_SMEM_BYTES);
    cudaFuncSetAttribute(mpn_mma_kernel<true>,  cudaFuncAttributeMaxDynamicSharedMemorySize, MPN_SMEM_BYTES);

    // 0. weight prep (tf32 cvt + fragment layout)
    wprep_kernel<<<144, 256>>>(k_mpn1, k_mpn2);
    // 1. MLP -> fm[:, 0:32] (masked)
    mlp_kernel<<<2048, 256, MLP_SMEM>>>(ray, zbufs, W1, b1, W2, b2, W3, b3, W4, b4, fm);
    // 2. sup conv1: 3->32 relu -> t1
    conv3x3_kernel<3,3,32,true><<<dim3(16,32,8), 256, SUP1_SMEM>>>(
        colors, k_sup1, b_sup1, t1, 0, 3*KK, 3, HWp*32, 32, 0);
    // 3. sup conv2: 32->32 -> fm[:, 32:64]
    conv3x3_kernel<32,8,32,false><<<dim3(16,32,8), 256, SUP2_SMEM>>>(
        t1, k_sup2, b_sup2, fm, HWp*32, 32, 0, HWp*64, 64, 32);
    // 4. mpn conv1 (mma tf32): 64->64 +bias relu -> t2
    mpn_mma_kernel<false><<<dim3(4,512), 256, MPN_SMEM_BYTES>>>(fm, wB, b_mpn1, t2, nullptr);
    // 5. mpn conv2 (mma tf32) + sigmoid + cumprod composite -> fuse
    mpn_mma_kernel<true><<<dim3(4,512), 256, MPN_SMEM_BYTES>>>(t2, wB + 36864, b_mpn2, fuse, fm);
    // 6. unet conv1: 8->32 relu -> u1
    conv3x3_kernel<8,8,32,true><<<dim3(16,32,1), 256, UN1_SMEM>>>(
        fuse, k_un1, b_un1, u1, 0, KK, 0, 0, 32, 0);
    // 7. unet conv2: 32->3 -> img
    unet2_kernel<<<dim3(32,32,1), 256>>>(u1, k_un2, b_un2, (float*)d_out);
}

// round 7
// speedup vs baseline: 2.9260x; 1.4750x over previous
#include <cuda_runtime.h>
#include <cstddef>
#include <cstdint>

#define Hh 512
#define Ww 512
#define KK 8
#define HWp (Hh*Ww)

typedef unsigned long long ull;

__device__ float g_t1[KK * HWp * 32];
__device__ float g_fm[KK * HWp * 64];
__device__ float g_t2[KK * HWp * 64];
__device__ float g_fuse[HWp * KK];
__device__ float g_u1[HWp * 32];
__device__ float g_wB[2 * 36864];   // prepped MPN weights (tf32 bits)
__device__ float g_wMLP[38912];     // prepped MLP weights (tf32 bits)

// ---------------- packed fp32x2 helpers ----------------
__device__ __forceinline__ ull pack2(float v) {
    ull r; asm("mov.b64 %0, {%1, %1};" : "=l"(r) : "f"(v)); return r;
}
__device__ __forceinline__ float2 unpack2(ull v) {
    float2 f; asm("mov.b64 {%0, %1}, %2;" : "=f"(f.x), "=f"(f.y) : "l"(v)); return f;
}
__device__ __forceinline__ void fma2(ull &d, ull a, ull b) {
    asm("fma.rn.f32x2 %0, %1, %2, %0;" : "+l"(d) : "l"(a), "l"(b));
}
__device__ __forceinline__ float to_tf32(float v) {
    uint32_t o; asm("cvt.rna.tf32.f32 %0, %1;" : "=r"(o) : "f"(v));
    return __uint_as_float(o);
}

// ---------------- warp mma tf32 m16n8k8 ----------------
__device__ __forceinline__ void mma_tf32(float* c,
                                         float a0, float a1, float a2, float a3,
                                         float b0, float b1)
{
    asm volatile(
        "mma.sync.aligned.m16n8k8.row.col.f32.tf32.tf32.f32 "
        "{%0,%1,%2,%3}, {%4,%5,%6,%7}, {%8,%9}, {%0,%1,%2,%3};"
        : "+f"(c[0]), "+f"(c[1]), "+f"(c[2]), "+f"(c[3])
        : "r"(__float_as_uint(a0)), "r"(__float_as_uint(a1)),
          "r"(__float_as_uint(a2)), "r"(__float_as_uint(a3)),
          "r"(__float_as_uint(b0)), "r"(__float_as_uint(b1)));
}

// =======================================================================
// Weight prep: MPN k [tap][cin][cout] HWIO -> [h][tap][g][co][c][s]
// =======================================================================
__global__ void wprep_kernel(const float* __restrict__ w1, const float* __restrict__ w2)
{
    int i = blockIdx.x * 256 + threadIdx.x;
    if (i >= 36864) return;
    int s   = i & 1;
    int c   = (i >> 1) & 3;
    int co  = (i >> 3) & 63;
    int blk = i >> 9;
    int g   = blk & 3;
    int ht  = blk >> 2;
    int h   = ht / 9, tap = ht - h * 9;
    int cin = h * 32 + g * 8 + c + s * 4;
    int src = (tap * 64 + cin) * 64 + co;
    g_wB[i]         = to_tf32(w1[src]);
    g_wB[36864 + i] = to_tf32(w2[src]);
}

// MLP weight prep -> [ks][n][cq][s], k = ks*8+cq+s*4, zero-padded
#define MW1 0
#define MW2 1024
#define MW3 17408
#define MW4 34816
__global__ void wprep_mlp_kernel(const float* __restrict__ W1, const float* __restrict__ W2,
                                 const float* __restrict__ W3, const float* __restrict__ W4)
{
    int i = blockIdx.x * 256 + threadIdx.x;
    if (i >= 38912) return;
    int base, Kin, N; const float* W;
    if (i < MW2)      { base = MW1; Kin = 3;   N = 128; W = W1; }
    else if (i < MW3) { base = MW2; Kin = 128; N = 128; W = W2; }
    else if (i < MW4) { base = MW3; Kin = 131; N = 128; W = W3; }
    else              { base = MW4; Kin = 128; N = 32;  W = W4; }
    int r  = i - base;
    int s  = r & 1;
    int cq = (r >> 1) & 3;
    int n  = (r >> 3) % N;
    int ks = (r >> 3) / N;
    int k  = ks * 8 + cq + s * 4;
    g_wMLP[i] = (k < Kin) ? to_tf32(W[k * N + n]) : 0.f;
}

// =======================================================================
// MLP via mma.sync tf32: warp = 16 samples; layers chained through smem.
// act stride 164 (=4 mod 32 -> conflict-free A fragment reads).
// =======================================================================
#define AST 164
#define MLP2_SMEM ((2*128*AST + 416 + 128) * 4)

template<int KS, int NCG>
__device__ __forceinline__ void mlp_layer(const float* __restrict__ ain,
                                          const float* __restrict__ wg,
                                          const float* __restrict__ bia,
                                          float* __restrict__ aout,
                                          int m0, int cq, int r)
{
    float c[NCG][4];
#pragma unroll
    for (int cg = 0; cg < NCG; cg++)
        c[cg][0] = c[cg][1] = c[cg][2] = c[cg][3] = 0.f;
    constexpr int N = NCG * 8;
#pragma unroll
    for (int ks = 0; ks < KS; ks++) {
        const float* ap = ain + m0 * AST + ks * 8 + cq;
        float a0 = ap[0], a2 = ap[4];
        float a1 = ap[8 * AST], a3 = ap[8 * AST + 4];
        const float2* wp = (const float2*)wg + ((size_t)ks * N + r) * 4 + cq;
#pragma unroll
        for (int cg = 0; cg < NCG; cg++) {
            float2 b = __ldg(&wp[cg * 32]);
            mma_tf32(c[cg], a0, a1, a2, a3, b.x, b.y);
        }
    }
#pragma unroll
    for (int cg = 0; cg < NCG; cg++) {
        int n = cg * 8 + cq * 2;
        float b0 = bia[n], b1 = bia[n + 1];
        float v0 = to_tf32(fmaxf(c[cg][0] + b0, 0.f));
        float v1 = to_tf32(fmaxf(c[cg][1] + b1, 0.f));
        float v2 = to_tf32(fmaxf(c[cg][2] + b0, 0.f));
        float v3 = to_tf32(fmaxf(c[cg][3] + b1, 0.f));
        *(float2*)(aout + m0 * AST + n)       = make_float2(v0, v1);
        *(float2*)(aout + (m0 + 8) * AST + n) = make_float2(v2, v3);
    }
}

__global__ __launch_bounds__(256, 1)
void mlp_mma_kernel(const float* __restrict__ ray, const float* __restrict__ zb,
                    const float* __restrict__ b1, const float* __restrict__ b2,
                    const float* __restrict__ b3, const float* __restrict__ b4,
                    const float* __restrict__ wmlp, float* __restrict__ fm)
{
    extern __shared__ float sh[];
    float* actA  = sh;
    float* actB  = sh + 128 * AST;
    float* sbias = sh + 2 * 128 * AST;   // 416
    float* smask = sbias + 416;          // 128

    const int tid = threadIdx.x;
    const int wrp = tid >> 5, lane = tid & 31;
    const int r = lane >> 2, cq = lane & 3;
    const int m0 = wrp * 16 + r;

    if (tid < 128) { sbias[tid] = b1[tid]; sbias[128 + tid] = b2[tid]; sbias[256 + tid] = b3[tid]; }
    if (tid < 32)  sbias[384 + tid] = b4[tid];
    __syncthreads();

    const int NT = (KK * HWp) / 128;
    for (int t = blockIdx.x; t < NT; t += gridDim.x) {
        if (tid < 128) {
            int sid = t * 128 + tid;
            int kk  = sid / HWp;
            int pix = sid - kk * HWp;
            const float* rp = ray + (size_t)pix * 7;
            float z  = zb[(size_t)pix * KK + kk];
            float tt = z / rp[6];
            float* A = actB + tid * AST;
            A[0] = to_tf32(rp[0] + rp[3] * tt);
            A[1] = to_tf32(rp[1] + rp[4] * tt);
            A[2] = to_tf32(rp[2] + rp[5] * tt);
            A[3] = 0.f; A[4] = 0.f; A[5] = 0.f; A[6] = 0.f; A[7] = 0.f;
            A[128] = to_tf32(rp[3]); A[129] = to_tf32(rp[4]); A[130] = to_tf32(rp[5]);
            A[131] = 0.f; A[132] = 0.f; A[133] = 0.f; A[134] = 0.f; A[135] = 0.f;
            smask[tid] = (z > 0.f) ? 1.f : 0.f;
        }
        __syncthreads();
        mlp_layer<1, 16>(actB, wmlp + MW1, sbias,       actA, m0, cq, r);
        __syncthreads();
        mlp_layer<16, 16>(actA, wmlp + MW2, sbias + 128, actB, m0, cq, r);
        __syncthreads();
        mlp_layer<17, 16>(actB, wmlp + MW3, sbias + 256, actA, m0, cq, r);
        __syncthreads();
        // L4: K=128, N=32, no relu, mask, store to fm[:,0:32]
        {
            float c[4][4];
#pragma unroll
            for (int cg = 0; cg < 4; cg++)
                c[cg][0] = c[cg][1] = c[cg][2] = c[cg][3] = 0.f;
#pragma unroll
            for (int ks = 0; ks < 16; ks++) {
                const float* ap = actA + m0 * AST + ks * 8 + cq;
                float a0 = ap[0], a2 = ap[4];
                float a1 = ap[8 * AST], a3 = ap[8 * AST + 4];
                const float2* wp = (const float2*)(wmlp + MW4) + ((size_t)ks * 32 + r) * 4 + cq;
#pragma unroll
                for (int cg = 0; cg < 4; cg++) {
                    float2 b = __ldg(&wp[cg * 32]);
                    mma_tf32(c[cg], a0, a1, a2, a3, b.x, b.y);
                }
            }
            float mf0 = smask[m0], mf8 = smask[m0 + 8];
            size_t s0 = (size_t)t * 128 + m0;
#pragma unroll
            for (int cg = 0; cg < 4; cg++) {
                int n = cg * 8 + cq * 2;
                float b0 = sbias[384 + n], b1v = sbias[384 + n + 1];
                *(float2*)(fm + s0 * 64 + n) =
                    make_float2((c[cg][0] + b0) * mf0, (c[cg][1] + b1v) * mf0);
                *(float2*)(fm + (s0 + 8) * 64 + n) =
                    make_float2((c[cg][2] + b0) * mf8, (c[cg][3] + b1v) * mf8);
            }
        }
        __syncthreads();
    }
}

// =======================================================================
// MPN conv 64->64 via mma.sync tf32 (unchanged R6, validated)
// =======================================================================
#define WST 40
#define SW_OFF 64
#define SA_OFF (64 + 36864)
#define MPN_SMEM_BYTES ((SA_OFF + 3*130*WST) * 4)

template<bool FUSE>
__global__ __launch_bounds__(256, 1)
void mpn_mma_kernel(const float* __restrict__ in, const float* __restrict__ wB,
                    const float* __restrict__ bias,
                    float* __restrict__ out, const float* __restrict__ fmc)
{
    extern __shared__ float sh[];
    float* s_bias = sh;
    float* s_w    = sh + SW_OFF;
    float* s_a    = sh + SA_OFF;
    float* s_l    = s_a;

    const int tid  = threadIdx.x;
    const int wrp  = tid >> 5, lane = tid & 31;
    const int r    = lane >> 2, cq = lane & 3;
    const int gx   = blockIdx.x * 128;
    const int y    = blockIdx.y;

    {
        const float4* src = (const float4*)wB;
        float4* dst = (float4*)s_w;
        for (int i = tid; i < 9216; i += 256) dst[i] = src[i];
        if (tid < 64) s_bias[tid] = bias[tid];
    }
    __syncthreads();

    float bia[8][2];
#pragma unroll
    for (int cg = 0; cg < 8; cg++) {
        bia[cg][0] = s_bias[cg * 8 + cq * 2];
        bia[cg][1] = s_bias[cg * 8 + cq * 2 + 1];
    }

    for (int k = 0; k < KK; k++) {
        float c[8][4];
#pragma unroll
        for (int cg = 0; cg < 8; cg++) {
            c[cg][0] = bia[cg][0]; c[cg][1] = bia[cg][1];
            c[cg][2] = bia[cg][0]; c[cg][3] = bia[cg][1];
        }
#pragma unroll 1
        for (int h = 0; h < 2; h++) {
            const float* inb = in + ((size_t)k * HWp) * 64 + h * 32;
            for (int it = tid; it < 1560; it += 256) {
                int ky  = it / 520;
                int rem = it - ky * 520;
                int p   = rem >> 2, g = rem & 3;
                int iy = y + ky - 1, ix = gx + p - 1;
                float4 lo = make_float4(0.f,0.f,0.f,0.f);
                float4 hi = make_float4(0.f,0.f,0.f,0.f);
                if ((unsigned)iy < Hh && (unsigned)ix < Ww) {
                    const float* q = inb + ((size_t)iy * Ww + ix) * 64 + g * 8;
                    lo = *(const float4*)q;
                    hi = *(const float4*)(q + 4);
                }
                float* d = s_a + (ky * 130 + p) * WST + g * 8;
                d[0] = lo.x; d[1] = hi.x; d[2] = lo.y; d[3] = hi.y;
                d[4] = lo.z; d[5] = hi.z; d[6] = lo.w; d[7] = hi.w;
            }
            __syncthreads();
#pragma unroll
            for (int tap = 0; tap < 9; tap++) {
                const int ky = tap / 3, kx = tap - ky * 3;
#pragma unroll
                for (int g = 0; g < 4; g++) {
                    const float* ap = s_a + (ky * 130 + kx + wrp * 16 + r) * WST + g * 8 + cq * 2;
                    float a0 = ap[0],         a2 = ap[1];
                    float a1 = ap[8 * WST],   a3 = ap[8 * WST + 1];
                    const float* wp = s_w + (((h * 9 + tap) * 4 + g) << 9) + r * 8 + cq * 2;
#pragma unroll
                    for (int cg = 0; cg < 8; cg++) {
                        float b0 = wp[cg * 64], b1 = wp[cg * 64 + 1];
                        mma_tf32(c[cg], a0, a1, a2, a3, b0, b1);
                    }
                }
            }
            __syncthreads();
        }

        if (!FUSE) {
            const size_t pixbase = (size_t)k * HWp + (size_t)y * Ww + gx + wrp * 16;
            float* o0 = out + (pixbase + r) * 64;
            float* o1 = out + (pixbase + r + 8) * 64;
#pragma unroll
            for (int cg = 0; cg < 8; cg++) {
                float2 v0 = make_float2(fmaxf(c[cg][0], 0.f), fmaxf(c[cg][1], 0.f));
                float2 v1 = make_float2(fmaxf(c[cg][2], 0.f), fmaxf(c[cg][3], 0.f));
                *(float2*)(o0 + cg * 8 + cq * 2) = v0;
                *(float2*)(o1 + cg * 8 + cq * 2) = v1;
            }
        } else {
            const int p0 = wrp * 16 + r;
#pragma unroll
            for (int cg = 0; cg < 8; cg++) {
                float* l0 = s_l + p0 * 65 + cg * 8 + cq * 2;
                l0[0] = c[cg][0]; l0[1] = c[cg][1];
                float* l1 = s_l + (p0 + 8) * 65 + cg * 8 + cq * 2;
                l1[0] = c[cg][2]; l1[1] = c[cg][3];
            }
            __syncthreads();
            if (tid < 128) {
                const int px = tid;
                const size_t pix = (size_t)y * Ww + gx + px;
                const float4* f4 = (const float4*)(fmc + ((size_t)k * HWp + pix) * 64);
                const float* lp = s_l + px * 65;
                float alpha = 1.f, fs = 0.f;
#pragma unroll
                for (int i = 0; i < 16; i++) {
                    float4 fv = __ldg(&f4[i]);
                    float l0 = lp[4*i], l1 = lp[4*i+1], l2 = lp[4*i+2], l3 = lp[4*i+3];
                    float m0 = 1.f / (1.f + __expf(-l0));
                    fs += fv.x * m0 * alpha; alpha *= (1.f - m0);
                    float m1 = 1.f / (1.f + __expf(-l1));
                    fs += fv.y * m1 * alpha; alpha *= (1.f - m1);
                    float m2 = 1.f / (1.f + __expf(-l2));
                    fs += fv.z * m2 * alpha; alpha *= (1.f - m2);
                    float m3 = 1.f / (1.f + __expf(-l3));
                    fs += fv.w * m3 * alpha; alpha *= (1.f - m3);
                }
                out[pix * KK + k] = fs;
            }
            __syncthreads();
        }
    }
}

// =======================================================================
// Direct 3x3 conv (fp32 FFMA2) — sup1/sup2/un1 (unchanged R3/R6)
// =======================================================================
template<int CIN, int CHUNK, int COUT, bool RELU>
__global__ __launch_bounds__(256, 2)
void conv3x3_kernel(const float* __restrict__ in, const float* __restrict__ wgt,
                    const float* __restrict__ bias, float* __restrict__ out,
                    int in_batch_stride, int in_pix_stride, int in_ch_per_n,
                    int out_batch_stride, int out_pix_stride, int out_ch_off)
{
    constexpr int NCG   = COUT / 16;
    constexpr int SLOTS = 256 / NCG;
    constexpr int TY    = SLOTS / 8;
    constexpr int HY    = TY + 2;
    constexpr int RS    = 37;
    constexpr int SIN   = ((CHUNK * HY * RS + 3) / 4) * 4;

    extern __shared__ float sh[];
    float* s_in = sh;
    float* s_w  = sh + SIN;

    const int tid  = threadIdx.x;
    const int cg   = tid / SLOTS;
    const int slot = tid % SLOTS;
    const int sx   = (slot & 7) * 4;
    const int sy   = slot >> 3;
    const int gx = blockIdx.x * 32, gy = blockIdx.y * TY;
    const int n  = blockIdx.z;

    const float* inb = in + (size_t)n * in_batch_stride;
    const int choff_n = n * in_ch_per_n;

    ull acc[4][8];
    {
        const ull* b2 = (const ull*)(bias + cg * 16);
#pragma unroll
        for (int j = 0; j < 8; j++) {
            ull bv = __ldg(&b2[j]);
#pragma unroll
            for (int p = 0; p < 4; p++) acc[p][j] = bv;
        }
    }
    for (int c0 = 0; c0 < CIN; c0 += CHUNK) {
        for (int idx = tid; idx < CHUNK * HY * 34; idx += 256) {
            int c   = idx / (HY * 34);
            int rem = idx - c * (HY * 34);
            int rr  = rem / 34;
            int j   = rem - rr * 34;
            int iy = gy - 1 + rr, ix = gx - 1 + j;
            float v = 0.f;
            if ((unsigned)iy < Hh && (unsigned)ix < Ww)
                v = inb[(size_t)(iy * Ww + ix) * in_pix_stride + choff_n + c0 + c];
            s_in[(c * HY + rr) * RS + j] = v;
        }
        for (int idx = tid; idx < 9 * CHUNK * COUT; idx += 256) {
            int tap = idx / (CHUNK * COUT);
            int rem = idx - tap * (CHUNK * COUT);
            int c   = rem / COUT;
            int co  = rem - c * COUT;
            s_w[idx] = wgt[(size_t)(tap * CIN + c0 + c) * COUT + co];
        }
        __syncthreads();
#pragma unroll
        for (int ky = 0; ky < 3; ky++) {
#pragma unroll
            for (int c = 0; c < CHUNK; c++) {
                const float* ip = s_in + ((c * HY) + sy + ky) * RS + sx;
                float a[6];
#pragma unroll
                for (int i = 0; i < 6; i++) a[i] = ip[i];
#pragma unroll
                for (int kx = 0; kx < 3; kx++) {
                    const ulonglong2* wp = (const ulonglong2*)
                        (s_w + ((ky * 3 + kx) * CHUNK + c) * COUT + cg * 16);
                    ulonglong2 w0 = wp[0], w1 = wp[1], w2 = wp[2], w3 = wp[3];
#pragma unroll
                    for (int p = 0; p < 4; p++) {
                        ull a2 = pack2(a[kx + p]);
                        fma2(acc[p][0], a2, w0.x); fma2(acc[p][1], a2, w0.y);
                        fma2(acc[p][2], a2, w1.x); fma2(acc[p][3], a2, w1.y);
                        fma2(acc[p][4], a2, w2.x); fma2(acc[p][5], a2, w2.y);
                        fma2(acc[p][6], a2, w3.x); fma2(acc[p][7], a2, w3.y);
                    }
                }
            }
        }
        __syncthreads();
    }
#pragma unroll
    for (int p = 0; p < 4; p++) {
        float* op = out + (size_t)n * out_batch_stride
                        + (size_t)((gy + sy) * Ww + gx + sx + p) * out_pix_stride
                        + out_ch_off + cg * 16;
#pragma unroll
        for (int i = 0; i < 4; i++) {
            float2 v0 = unpack2(acc[p][2*i]), v1 = unpack2(acc[p][2*i+1]);
            float4 o = make_float4(v0.x, v0.y, v1.x, v1.y);
            if (RELU) { o.x=fmaxf(o.x,0.f); o.y=fmaxf(o.y,0.f); o.z=fmaxf(o.z,0.f); o.w=fmaxf(o.w,0.f); }
            *(float4*)(op + 4*i) = o;
        }
    }
}

// =======================================================================
// unet conv2: 32 -> 3 (unchanged R3)
// =======================================================================
__global__ __launch_bounds__(256)
void unet2_kernel(const float* __restrict__ in, const float* __restrict__ wgt,
                  const float* __restrict__ bias, float* __restrict__ out)
{
    constexpr int CIN = 32, CHUNK = 16, SP = CHUNK + 1;
    __shared__ float s_in[324 * SP];
    __shared__ float s_w[9 * CHUNK * 3];

    const int tid = threadIdx.x;
    const int tx = tid & 15, ty = tid >> 4;
    const int gx = blockIdx.x * 16, gy = blockIdx.y * 16;

    float acc0 = __ldg(&bias[0]), acc1 = __ldg(&bias[1]), acc2 = __ldg(&bias[2]);

    for (int c0 = 0; c0 < CIN; c0 += CHUNK) {
        for (int idx = tid; idx < 324 * CHUNK; idx += 256) {
            int p = idx / CHUNK, c = idx - p * CHUNK;
            int py = p / 18, px = p - py * 18;
            int iy = gy - 1 + py, ix = gx - 1 + px;
            float v = 0.f;
            if ((unsigned)iy < Hh && (unsigned)ix < Ww)
                v = in[(size_t)(iy * Ww + ix) * CIN + c0 + c];
            s_in[p * SP + c] = v;
        }
        for (int idx = tid; idx < 9 * CHUNK * 3; idx += 256) {
            int tap = idx / (CHUNK * 3);
            int r   = idx - tap * (CHUNK * 3);
            int c   = r / 3, co = r - c * 3;
            s_w[idx] = wgt[(size_t)(tap * CIN + c0 + c) * 3 + co];
        }
        __syncthreads();
#pragma unroll
        for (int tap = 0; tap < 9; tap++) {
            int ky = tap / 3, kx = tap - ky * 3;
            const float* ip = s_in + ((ty + ky) * 18 + tx + kx) * SP;
            const float* wp = s_w + tap * CHUNK * 3;
#pragma unroll
            for (int c = 0; c < CHUNK; c++) {
                float a = ip[c];
                acc0 += a * wp[c*3 + 0];
                acc1 += a * wp[c*3 + 1];
                acc2 += a * wp[c*3 + 2];
            }
        }
        __syncthreads();
    }
    float* op = out + (size_t)((gy + ty) * Ww + gx + tx) * 3;
    op[0] = acc0; op[1] = acc1; op[2] = acc2;
}

// =======================================================================
extern "C" void kernel_launch(void* const* d_in, const int* in_sizes, int n_in,
                              void* d_out, int out_size)
{
    const float* colors = (const float*)d_in[0];
    const float* ray    = (const float*)d_in[1];
    const float* zbufs  = (const float*)d_in[2];
    const float* W1 = (const float*)d_in[3];  const float* b1 = (const float*)d_in[4];
    const float* W2 = (const float*)d_in[5];  const float* b2 = (const float*)d_in[6];
    const float* W3 = (const float*)d_in[7];  const float* b3 = (const float*)d_in[8];
    const float* W4 = (const float*)d_in[9];  const float* b4 = (const float*)d_in[10];
    const float* k_sup1 = (const float*)d_in[11]; const float* b_sup1 = (const float*)d_in[12];
    const float* k_sup2 = (const float*)d_in[13]; const float* b_sup2 = (const float*)d_in[14];
    const float* k_mpn1 = (const float*)d_in[15]; const float* b_mpn1 = (const float*)d_in[16];
    const float* k_mpn2 = (const float*)d_in[17]; const float* b_mpn2 = (const float*)d_in[18];
    const float* k_un1  = (const float*)d_in[19]; const float* b_un1  = (const float*)d_in[20];
    const float* k_un2  = (const float*)d_in[21]; const float* b_un2  = (const float*)d_in[22];

    float *t1, *fm, *t2, *fuse, *u1, *wB, *wM;
    cudaGetSymbolAddress((void**)&t1,   g_t1);
    cudaGetSymbolAddress((void**)&fm,   g_fm);
    cudaGetSymbolAddress((void**)&t2,   g_t2);
    cudaGetSymbolAddress((void**)&fuse, g_fuse);
    cudaGetSymbolAddress((void**)&u1,   g_u1);
    cudaGetSymbolAddress((void**)&wB,   g_wB);
    cudaGetSymbolAddress((void**)&wM,   g_wMLP);

    auto A4 = [](int x){ return ((x + 3) / 4) * 4; };
    const int SUP1_SMEM = (A4(3*18*37) + 9*3*32) * 4;
    const int SUP2_SMEM = (A4(8*18*37) + 9*8*32) * 4;
    const int UN1_SMEM  = (A4(8*18*37) + 9*8*32) * 4;

    cudaFuncSetAttribute(mlp_mma_kernel, cudaFuncAttributeMaxDynamicSharedMemorySize, MLP2_SMEM);
    cudaFuncSetAttribute(mpn_mma_kernel<false>, cudaFuncAttributeMaxDynamicSharedMemorySize, MPN_SMEM_BYTES);
    cudaFuncSetAttribute(mpn_mma_kernel<true>,  cudaFuncAttributeMaxDynamicSharedMemorySize, MPN_SMEM_BYTES);

    // 0. weight prep (tf32 cvt + fragment layouts)
    wprep_kernel<<<144, 256>>>(k_mpn1, k_mpn2);
    wprep_mlp_kernel<<<152, 256>>>(W1, W2, W3, W4);
    // 1. MLP (mma tf32) -> fm[:, 0:32] (masked)
    mlp_mma_kernel<<<2048, 256, MLP2_SMEM>>>(ray, zbufs, b1, b2, b3, b4, wM, fm);
    // 2. sup conv1: 3->32 relu -> t1
    conv3x3_kernel<3,3,32,true><<<dim3(16,32,8), 256, SUP1_SMEM>>>(
        colors, k_sup1, b_sup1, t1, 0, 3*KK, 3, HWp*32, 32, 0);
    // 3. sup conv2: 32->32 -> fm[:, 32:64]
    conv3x3_kernel<32,8,32,false><<<dim3(16,32,8), 256, SUP2_SMEM>>>(
        t1, k_sup2, b_sup2, fm, HWp*32, 32, 0, HWp*64, 64, 32);
    // 4. mpn conv1 (mma tf32): 64->64 +bias relu -> t2
    mpn_mma_kernel<false><<<dim3(4,512), 256, MPN_SMEM_BYTES>>>(fm, wB, b_mpn1, t2, nullptr);
    // 5. mpn conv2 (mma tf32) + sigmoid + cumprod composite -> fuse
    mpn_mma_kernel<true><<<dim3(4,512), 256, MPN_SMEM_BYTES>>>(t2, wB + 36864, b_mpn2, fuse, fm);
    // 6. unet conv1: 8->32 relu -> u1
    conv3x3_kernel<8,8,32,true><<<dim3(16,32,1), 256, UN1_SMEM>>>(
        fuse, k_un1, b_un1, u1, 0, KK, 0, 0, 32, 0);
    // 7. unet conv2: 32->3 -> img
    unet2_kernel<<<dim3(32,32,1), 256>>>(u1, k_un2, b_un2, (float*)d_out);
}

// round 8
// speedup vs baseline: 3.2129x; 1.0980x over previous
#include <cuda_runtime.h>
#include <cstddef>
#include <cstdint>

#define Hh 512
#define Ww 512
#define KK 8
#define HWp (Hh*Ww)

typedef unsigned long long ull;

__device__ float g_t1[KK * HWp * 32];     // sup1 out
__device__ float g_feat[KK * HWp * 32];   // MLP out (masked)
__device__ float g_fc[KK * HWp * 32];     // sup2 out
__device__ float g_t2[KK * HWp * 64];     // mpn1 out
__device__ float g_fuse[HWp * KK];
__device__ float g_u1[HWp * 32];
__device__ float g_wB[2 * 36864];   // prepped MPN weights (tf32 bits)
__device__ float g_wS[9216];        // prepped sup2 weights (tf32 bits)
__device__ float g_wMLP[38912];     // prepped MLP weights (tf32 bits)

// ---------------- packed fp32x2 helpers ----------------
__device__ __forceinline__ ull pack2(float v) {
    ull r; asm("mov.b64 %0, {%1, %1};" : "=l"(r) : "f"(v)); return r;
}
__device__ __forceinline__ float2 unpack2(ull v) {
    float2 f; asm("mov.b64 {%0, %1}, %2;" : "=f"(f.x), "=f"(f.y) : "l"(v)); return f;
}
__device__ __forceinline__ void fma2(ull &d, ull a, ull b) {
    asm("fma.rn.f32x2 %0, %1, %2, %0;" : "+l"(d) : "l"(a), "l"(b));
}
__device__ __forceinline__ float to_tf32(float v) {
    uint32_t o; asm("cvt.rna.tf32.f32 %0, %1;" : "=r"(o) : "f"(v));
    return __uint_as_float(o);
}

// ---------------- warp mma tf32 m16n8k8 ----------------
__device__ __forceinline__ void mma_tf32(float* c,
                                         float a0, float a1, float a2, float a3,
                                         float b0, float b1)
{
    asm volatile(
        "mma.sync.aligned.m16n8k8.row.col.f32.tf32.tf32.f32 "
        "{%0,%1,%2,%3}, {%4,%5,%6,%7}, {%8,%9}, {%0,%1,%2,%3};"
        : "+f"(c[0]), "+f"(c[1]), "+f"(c[2]), "+f"(c[3])
        : "r"(__float_as_uint(a0)), "r"(__float_as_uint(a1)),
          "r"(__float_as_uint(a2)), "r"(__float_as_uint(a3)),
          "r"(__float_as_uint(b0)), "r"(__float_as_uint(b1)));
}

// =======================================================================
// Weight preps
// =======================================================================
__global__ void wprep_kernel(const float* __restrict__ w1, const float* __restrict__ w2)
{
    int i = blockIdx.x * 256 + threadIdx.x;
    if (i >= 36864) return;
    int s   = i & 1;
    int c   = (i >> 1) & 3;
    int co  = (i >> 3) & 63;
    int blk = i >> 9;
    int g   = blk & 3;
    int ht  = blk >> 2;
    int h   = ht / 9, tap = ht - h * 9;
    int cin = h * 32 + g * 8 + c + s * 4;
    int src = (tap * 64 + cin) * 64 + co;
    g_wB[i]         = to_tf32(w1[src]);
    g_wB[36864 + i] = to_tf32(w2[src]);
}

__global__ void wprep_sup_kernel(const float* __restrict__ w)
{
    int i = blockIdx.x * 256 + threadIdx.x;
    if (i >= 9216) return;
    int s   = i & 1;
    int c   = (i >> 1) & 3;
    int co  = (i >> 3) & 31;
    int blk = i >> 8;
    int g   = blk & 3;
    int tap = blk >> 2;
    int cin = g * 8 + c + s * 4;
    g_wS[i] = to_tf32(w[(tap * 32 + cin) * 32 + co]);
}

#define MW1 0
#define MW2 1024
#define MW3 17408
#define MW4 34816
__global__ void wprep_mlp_kernel(const float* __restrict__ W1, const float* __restrict__ W2,
                                 const float* __restrict__ W3, const float* __restrict__ W4)
{
    int i = blockIdx.x * 256 + threadIdx.x;
    if (i >= 38912) return;
    int base, Kin, N; const float* W;
    if (i < MW2)      { base = MW1; Kin = 3;   N = 128; W = W1; }
    else if (i < MW3) { base = MW2; Kin = 128; N = 128; W = W2; }
    else if (i < MW4) { base = MW3; Kin = 131; N = 128; W = W3; }
    else              { base = MW4; Kin = 128; N = 32;  W = W4; }
    int r  = i - base;
    int s  = r & 1;
    int cq = (r >> 1) & 3;
    int n  = (r >> 3) % N;
    int ks = (r >> 3) / N;
    int k  = ks * 8 + cq + s * 4;
    g_wMLP[i] = (k < Kin) ? to_tf32(W[k * N + n]) : 0.f;
}

// =======================================================================
// Generalized 3x3 conv via mma.sync tf32.
// NH cin-halves (32 each), NCG cout-groups (8 each).  CTA = 128-px x-strip.
// in0/in1: base pointer per half (pixel stride = pixst, channel offset in ptr).
// !FUSE: +bias(+relu) -> out stride ost.  FUSE: +bias, sigmoid+cumprod with
// feat/fc (stride 32 each) -> g_fuse layout out[pix*KK + k].
// =======================================================================
#define WST 40

template<int NH, int NCG, bool RELU, bool FUSE>
__global__ __launch_bounds__(256, 1)
void gconv_mma_kernel(const float* __restrict__ in0, const float* __restrict__ in1,
                      int pixst,
                      const float* __restrict__ wB, const float* __restrict__ bias,
                      float* __restrict__ out, int ost,
                      const float* __restrict__ fm0, const float* __restrict__ fm1)
{
    extern __shared__ float sh[];
    float* s_bias = sh;
    float* s_w    = sh + 64;
    float* s_a    = sh + 64 + NH * 36 * NCG * 64;
    float* s_l    = s_a;

    const int tid  = threadIdx.x;
    const int wrp  = tid >> 5, lane = tid & 31;
    const int r    = lane >> 2, cq = lane & 3;
    const int gx   = blockIdx.x * 128;
    const int y    = blockIdx.y;

    {
        const float4* src = (const float4*)wB;
        float4* dst = (float4*)s_w;
        for (int i = tid; i < NH * 36 * NCG * 16; i += 256) dst[i] = src[i];
        if (tid < NCG * 8) s_bias[tid] = bias[tid];
    }
    __syncthreads();

    float bia[NCG][2];
#pragma unroll
    for (int cg = 0; cg < NCG; cg++) {
        bia[cg][0] = s_bias[cg * 8 + cq * 2];
        bia[cg][1] = s_bias[cg * 8 + cq * 2 + 1];
    }

    for (int k = 0; k < KK; k++) {
        float c[NCG][4];
#pragma unroll
        for (int cg = 0; cg < NCG; cg++) {
            c[cg][0] = bia[cg][0]; c[cg][1] = bia[cg][1];
            c[cg][2] = bia[cg][0]; c[cg][3] = bia[cg][1];
        }
#pragma unroll 1
        for (int h = 0; h < NH; h++) {
            const float* inb = (h == 0 ? in0 : in1) + (size_t)k * HWp * pixst;
            for (int it = tid; it < 1560; it += 256) {
                int ky  = it / 520;
                int rem = it - ky * 520;
                int p   = rem >> 2, g = rem & 3;
                int iy = y + ky - 1, ix = gx + p - 1;
                float4 lo = make_float4(0.f,0.f,0.f,0.f);
                float4 hi = make_float4(0.f,0.f,0.f,0.f);
                if ((unsigned)iy < Hh && (unsigned)ix < Ww) {
                    const float* q = inb + ((size_t)iy * Ww + ix) * pixst + g * 8;
                    lo = *(const float4*)q;
                    hi = *(const float4*)(q + 4);
                }
                float* d = s_a + (ky * 130 + p) * WST + g * 8;
                d[0] = lo.x; d[1] = hi.x; d[2] = lo.y; d[3] = hi.y;
                d[4] = lo.z; d[5] = hi.z; d[6] = lo.w; d[7] = hi.w;
            }
            __syncthreads();
#pragma unroll
            for (int tap = 0; tap < 9; tap++) {
                const int ky = tap / 3, kx = tap - ky * 3;
#pragma unroll
                for (int g = 0; g < 4; g++) {
                    const float* ap = s_a + (ky * 130 + kx + wrp * 16 + r) * WST + g * 8 + cq * 2;
                    float a0 = ap[0],         a2 = ap[1];
                    float a1 = ap[8 * WST],   a3 = ap[8 * WST + 1];
                    const float* wp = s_w + ((h * 9 + tap) * 4 + g) * (NCG * 64) + r * 8 + cq * 2;
#pragma unroll
                    for (int cg = 0; cg < NCG; cg++) {
                        float b0 = wp[cg * 64], b1 = wp[cg * 64 + 1];
                        mma_tf32(c[cg], a0, a1, a2, a3, b0, b1);
                    }
                }
            }
            __syncthreads();
        }

        if (!FUSE) {
            const size_t pixbase = (size_t)k * HWp + (size_t)y * Ww + gx + wrp * 16;
            float* o0 = out + (pixbase + r) * ost;
            float* o1 = out + (pixbase + r + 8) * ost;
#pragma unroll
            for (int cg = 0; cg < NCG; cg++) {
                float2 v0, v1;
                if (RELU) {
                    v0 = make_float2(fmaxf(c[cg][0], 0.f), fmaxf(c[cg][1], 0.f));
                    v1 = make_float2(fmaxf(c[cg][2], 0.f), fmaxf(c[cg][3], 0.f));
                } else {
                    v0 = make_float2(c[cg][0], c[cg][1]);
                    v1 = make_float2(c[cg][2], c[cg][3]);
                }
                *(float2*)(o0 + cg * 8 + cq * 2) = v0;
                *(float2*)(o1 + cg * 8 + cq * 2) = v1;
            }
        } else {
            const int p0 = wrp * 16 + r;
#pragma unroll
            for (int cg = 0; cg < NCG; cg++) {
                float* l0 = s_l + p0 * 65 + cg * 8 + cq * 2;
                l0[0] = c[cg][0]; l0[1] = c[cg][1];
                float* l1 = s_l + (p0 + 8) * 65 + cg * 8 + cq * 2;
                l1[0] = c[cg][2]; l1[1] = c[cg][3];
            }
            __syncthreads();
            if (tid < 128) {
                const int px = tid;
                const size_t pix = (size_t)y * Ww + gx + px;
                const float4* fa = (const float4*)(fm0 + ((size_t)k * HWp + pix) * 32);
                const float4* fb = (const float4*)(fm1 + ((size_t)k * HWp + pix) * 32);
                const float* lp = s_l + px * 65;
                float alpha = 1.f, fs = 0.f;
#pragma unroll
                for (int i = 0; i < 16; i++) {
                    float4 fv = (i < 8) ? __ldg(&fa[i]) : __ldg(&fb[i - 8]);
                    float l0 = lp[4*i], l1 = lp[4*i+1], l2 = lp[4*i+2], l3 = lp[4*i+3];
                    float m0 = 1.f / (1.f + __expf(-l0));
                    fs += fv.x * m0 * alpha; alpha *= (1.f - m0);
                    float m1 = 1.f / (1.f + __expf(-l1));
                    fs += fv.y * m1 * alpha; alpha *= (1.f - m1);
                    float m2 = 1.f / (1.f + __expf(-l2));
                    fs += fv.z * m2 * alpha; alpha *= (1.f - m2);
                    float m3 = 1.f / (1.f + __expf(-l3));
                    fs += fv.w * m3 * alpha; alpha *= (1.f - m3);
                }
                out[pix * KK + k] = fs;
            }
            __syncthreads();
        }
    }
}

// =======================================================================
// MLP via mma.sync tf32 (R7, feat output stride 32)
// =======================================================================
#define AST 164
#define MLP2_SMEM ((2*128*AST + 416 + 128) * 4)

template<int KS, int NCG>
__device__ __forceinline__ void mlp_layer(const float* __restrict__ ain,
                                          const float* __restrict__ wg,
                                          const float* __restrict__ bia,
                                          float* __restrict__ aout,
                                          int m0, int cq, int r)
{
    float c[NCG][4];
#pragma unroll
    for (int cg = 0; cg < NCG; cg++)
        c[cg][0] = c[cg][1] = c[cg][2] = c[cg][3] = 0.f;
    constexpr int N = NCG * 8;
#pragma unroll
    for (int ks = 0; ks < KS; ks++) {
        const float* ap = ain + m0 * AST + ks * 8 + cq;
        float a0 = ap[0], a2 = ap[4];
        float a1 = ap[8 * AST], a3 = ap[8 * AST + 4];
        const float2* wp = (const float2*)wg + ((size_t)ks * N + r) * 4 + cq;
#pragma unroll
        for (int cg = 0; cg < NCG; cg++) {
            float2 b = __ldg(&wp[cg * 32]);
            mma_tf32(c[cg], a0, a1, a2, a3, b.x, b.y);
        }
    }
#pragma unroll
    for (int cg = 0; cg < NCG; cg++) {
        int n = cg * 8 + cq * 2;
        float b0 = bia[n], b1 = bia[n + 1];
        float v0 = to_tf32(fmaxf(c[cg][0] + b0, 0.f));
        float v1 = to_tf32(fmaxf(c[cg][1] + b1, 0.f));
        float v2 = to_tf32(fmaxf(c[cg][2] + b0, 0.f));
        float v3 = to_tf32(fmaxf(c[cg][3] + b1, 0.f));
        *(float2*)(aout + m0 * AST + n)       = make_float2(v0, v1);
        *(float2*)(aout + (m0 + 8) * AST + n) = make_float2(v2, v3);
    }
}

__global__ __launch_bounds__(256, 1)
void mlp_mma_kernel(const float* __restrict__ ray, const float* __restrict__ zb,
                    const float* __restrict__ b1, const float* __restrict__ b2,
                    const float* __restrict__ b3, const float* __restrict__ b4,
                    const float* __restrict__ wmlp, float* __restrict__ feat)
{
    extern __shared__ float sh[];
    float* actA  = sh;
    float* actB  = sh + 128 * AST;
    float* sbias = sh + 2 * 128 * AST;
    float* smask = sbias + 416;

    const int tid = threadIdx.x;
    const int wrp = tid >> 5, lane = tid & 31;
    const int r = lane >> 2, cq = lane & 3;
    const int m0 = wrp * 16 + r;

    if (tid < 128) { sbias[tid] = b1[tid]; sbias[128 + tid] = b2[tid]; sbias[256 + tid] = b3[tid]; }
    if (tid < 32)  sbias[384 + tid] = b4[tid];
    __syncthreads();

    const int NT = (KK * HWp) / 128;
    for (int t = blockIdx.x; t < NT; t += gridDim.x) {
        if (tid < 128) {
            int sid = t * 128 + tid;
            int kk  = sid / HWp;
            int pix = sid - kk * HWp;
            const float* rp = ray + (size_t)pix * 7;
            float z  = zb[(size_t)pix * KK + kk];
            float tt = z / rp[6];
            float* A = actB + tid * AST;
            A[0] = to_tf32(rp[0] + rp[3] * tt);
            A[1] = to_tf32(rp[1] + rp[4] * tt);
            A[2] = to_tf32(rp[2] + rp[5] * tt);
            A[3] = 0.f; A[4] = 0.f; A[5] = 0.f; A[6] = 0.f; A[7] = 0.f;
            A[128] = to_tf32(rp[3]); A[129] = to_tf32(rp[4]); A[130] = to_tf32(rp[5]);
            A[131] = 0.f; A[132] = 0.f; A[133] = 0.f; A[134] = 0.f; A[135] = 0.f;
            smask[tid] = (z > 0.f) ? 1.f : 0.f;
        }
        __syncthreads();
        mlp_layer<1, 16>(actB, wmlp + MW1, sbias,       actA, m0, cq, r);
        __syncthreads();
        mlp_layer<16, 16>(actA, wmlp + MW2, sbias + 128, actB, m0, cq, r);
        __syncthreads();
        mlp_layer<17, 16>(actB, wmlp + MW3, sbias + 256, actA, m0, cq, r);
        __syncthreads();
        {
            float c[4][4];
#pragma unroll
            for (int cg = 0; cg < 4; cg++)
                c[cg][0] = c[cg][1] = c[cg][2] = c[cg][3] = 0.f;
#pragma unroll
            for (int ks = 0; ks < 16; ks++) {
                const float* ap = actA + m0 * AST + ks * 8 + cq;
                float a0 = ap[0], a2 = ap[4];
                float a1 = ap[8 * AST], a3 = ap[8 * AST + 4];
                const float2* wp = (const float2*)(wmlp + MW4) + ((size_t)ks * 32 + r) * 4 + cq;
#pragma unroll
                for (int cg = 0; cg < 4; cg++) {
                    float2 b = __ldg(&wp[cg * 32]);
                    mma_tf32(c[cg], a0, a1, a2, a3, b.x, b.y);
                }
            }
            float mf0 = smask[m0], mf8 = smask[m0 + 8];
            size_t s0 = (size_t)t * 128 + m0;
#pragma unroll
            for (int cg = 0; cg < 4; cg++) {
                int n = cg * 8 + cq * 2;
                float b0 = sbias[384 + n], b1v = sbias[384 + n + 1];
                *(float2*)(feat + s0 * 32 + n) =
                    make_float2((c[cg][0] + b0) * mf0, (c[cg][1] + b1v) * mf0);
                *(float2*)(feat + (s0 + 8) * 32 + n) =
                    make_float2((c[cg][2] + b0) * mf8, (c[cg][3] + b1v) * mf8);
            }
        }
        __syncthreads();
    }
}

// =======================================================================
// Direct 3x3 conv (fp32 FFMA2) — sup1/un1
// =======================================================================
template<int CIN, int CHUNK, int COUT, bool RELU>
__global__ __launch_bounds__(256, 2)
void conv3x3_kernel(const float* __restrict__ in, const float* __restrict__ wgt,
                    const float* __restrict__ bias, float* __restrict__ out,
                    int in_batch_stride, int in_pix_stride, int in_ch_per_n,
                    int out_batch_stride, int out_pix_stride, int out_ch_off)
{
    constexpr int NCG   = COUT / 16;
    constexpr int SLOTS = 256 / NCG;
    constexpr int TY    = SLOTS / 8;
    constexpr int HY    = TY + 2;
    constexpr int RS    = 37;
    constexpr int SIN   = ((CHUNK * HY * RS + 3) / 4) * 4;

    extern __shared__ float sh[];
    float* s_in = sh;
    float* s_w  = sh + SIN;

    const int tid  = threadIdx.x;
    const int cg   = tid / SLOTS;
    const int slot = tid % SLOTS;
    const int sx   = (slot & 7) * 4;
    const int sy   = slot >> 3;
    const int gx = blockIdx.x * 32, gy = blockIdx.y * TY;
    const int n  = blockIdx.z;

    const float* inb = in + (size_t)n * in_batch_stride;
    const int choff_n = n * in_ch_per_n;

    ull acc[4][8];
    {
        const ull* b2 = (const ull*)(bias + cg * 16);
#pragma unroll
        for (int j = 0; j < 8; j++) {
            ull bv = __ldg(&b2[j]);
#pragma unroll
            for (int p = 0; p < 4; p++) acc[p][j] = bv;
        }
    }
    for (int c0 = 0; c0 < CIN; c0 += CHUNK) {
        for (int idx = tid; idx < CHUNK * HY * 34; idx += 256) {
            int c   = idx / (HY * 34);
            int rem = idx - c * (HY * 34);
            int rr  = rem / 34;
            int j   = rem - rr * 34;
            int iy = gy - 1 + rr, ix = gx - 1 + j;
            float v = 0.f;
            if ((unsigned)iy < Hh && (unsigned)ix < Ww)
                v = inb[(size_t)(iy * Ww + ix) * in_pix_stride + choff_n + c0 + c];
            s_in[(c * HY + rr) * RS + j] = v;
        }
        for (int idx = tid; idx < 9 * CHUNK * COUT; idx += 256) {
            int tap = idx / (CHUNK * COUT);
            int rem = idx - tap * (CHUNK * COUT);
            int c   = rem / COUT;
            int co  = rem - c * COUT;
            s_w[idx] = wgt[(size_t)(tap * CIN + c0 + c) * COUT + co];
        }
        __syncthreads();
#pragma unroll
        for (int ky = 0; ky < 3; ky++) {
#pragma unroll
            for (int c = 0; c < CHUNK; c++) {
                const float* ip = s_in + ((c * HY) + sy + ky) * RS + sx;
                float a[6];
#pragma unroll
                for (int i = 0; i < 6; i++) a[i] = ip[i];
#pragma unroll
                for (int kx = 0; kx < 3; kx++) {
                    const ulonglong2* wp = (const ulonglong2*)
                        (s_w + ((ky * 3 + kx) * CHUNK + c) * COUT + cg * 16);
                    ulonglong2 w0 = wp[0], w1 = wp[1], w2 = wp[2], w3 = wp[3];
#pragma unroll
                    for (int p = 0; p < 4; p++) {
                        ull a2 = pack2(a[kx + p]);
                        fma2(acc[p][0], a2, w0.x); fma2(acc[p][1], a2, w0.y);
                        fma2(acc[p][2], a2, w1.x); fma2(acc[p][3], a2, w1.y);
                        fma2(acc[p][4], a2, w2.x); fma2(acc[p][5], a2, w2.y);
                        fma2(acc[p][6], a2, w3.x); fma2(acc[p][7], a2, w3.y);
                    }
                }
            }
        }
        __syncthreads();
    }
#pragma unroll
    for (int p = 0; p < 4; p++) {
        float* op = out + (size_t)n * out_batch_stride
                        + (size_t)((gy + sy) * Ww + gx + sx + p) * out_pix_stride
                        + out_ch_off + cg * 16;
#pragma unroll
        for (int i = 0; i < 4; i++) {
            float2 v0 = unpack2(acc[p][2*i]), v1 = unpack2(acc[p][2*i+1]);
            float4 o = make_float4(v0.x, v0.y, v1.x, v1.y);
            if (RELU) { o.x=fmaxf(o.x,0.f); o.y=fmaxf(o.y,0.f); o.z=fmaxf(o.z,0.f); o.w=fmaxf(o.w,0.f); }
            *(float4*)(op + 4*i) = o;
        }
    }
}

// =======================================================================
// unet conv2: 32 -> 3
// =======================================================================
__global__ __launch_bounds__(256)
void unet2_kernel(const float* __restrict__ in, const float* __restrict__ wgt,
                  const float* __restrict__ bias, float* __restrict__ out)
{
    constexpr int CIN = 32, CHUNK = 16, SP = CHUNK + 1;
    __shared__ float s_in[324 * SP];
    __shared__ float s_w[9 * CHUNK * 3];

    const int tid = threadIdx.x;
    const int tx = tid & 15, ty = tid >> 4;
    const int gx = blockIdx.x * 16, gy = blockIdx.y * 16;

    float acc0 = __ldg(&bias[0]), acc1 = __ldg(&bias[1]), acc2 = __ldg(&bias[2]);

    for (int c0 = 0; c0 < CIN; c0 += CHUNK) {
        for (int idx = tid; idx < 324 * CHUNK; idx += 256) {
            int p = idx / CHUNK, c = idx - p * CHUNK;
            int py = p / 18, px = p - py * 18;
            int iy = gy - 1 + py, ix = gx - 1 + px;
            float v = 0.f;
            if ((unsigned)iy < Hh && (unsigned)ix < Ww)
                v = in[(size_t)(iy * Ww + ix) * CIN + c0 + c];
            s_in[p * SP + c] = v;
        }
        for (int idx = tid; idx < 9 * CHUNK * 3; idx += 256) {
            int tap = idx / (CHUNK * 3);
            int r   = idx - tap * (CHUNK * 3);
            int c   = r / 3, co = r - c * 3;
            s_w[idx] = wgt[(size_t)(tap * CIN + c0 + c) * 3 + co];
        }
        __syncthreads();
#pragma unroll
        for (int tap = 0; tap < 9; tap++) {
            int ky = tap / 3, kx = tap - ky * 3;
            const float* ip = s_in + ((ty + ky) * 18 + tx + kx) * SP;
            const float* wp = s_w + tap * CHUNK * 3;
#pragma unroll
            for (int c = 0; c < CHUNK; c++) {
                float a = ip[c];
                acc0 += a * wp[c*3 + 0];
                acc1 += a * wp[c*3 + 1];
                acc2 += a * wp[c*3 + 2];
            }
        }
        __syncthreads();
    }
    float* op = out + (size_t)((gy + ty) * Ww + gx + tx) * 3;
    op[0] = acc0; op[1] = acc1; op[2] = acc2;
}

// =======================================================================
extern "C" void kernel_launch(void* const* d_in, const int* in_sizes, int n_in,
                              void* d_out, int out_size)
{
    const float* colors = (const float*)d_in[0];
    const float* ray    = (const float*)d_in[1];
    const float* zbufs  = (const float*)d_in[2];
    const float* W1 = (const float*)d_in[3];  const float* b1 = (const float*)d_in[4];
    const float* W2 = (const float*)d_in[5];  const float* b2 = (const float*)d_in[6];
    const float* W3 = (const float*)d_in[7];  const float* b3 = (const float*)d_in[8];
    const float* W4 = (const float*)d_in[9];  const float* b4 = (const float*)d_in[10];
    const float* k_sup1 = (const float*)d_in[11]; const float* b_sup1 = (const float*)d_in[12];
    const float* k_sup2 = (const float*)d_in[13]; const float* b_sup2 = (const float*)d_in[14];
    const float* k_mpn1 = (const float*)d_in[15]; const float* b_mpn1 = (const float*)d_in[16];
    const float* k_mpn2 = (const float*)d_in[17]; const float* b_mpn2 = (const float*)d_in[18];
    const float* k_un1  = (const float*)d_in[19]; const float* b_un1  = (const float*)d_in[20];
    const float* k_un2  = (const float*)d_in[21]; const float* b_un2  = (const float*)d_in[22];

    float *t1, *feat, *fc, *t2, *fuse, *u1, *wB, *wS, *wM;
    cudaGetSymbolAddress((void**)&t1,   g_t1);
    cudaGetSymbolAddress((void**)&feat, g_feat);
    cudaGetSymbolAddress((void**)&fc,   g_fc);
    cudaGetSymbolAddress((void**)&t2,   g_t2);
    cudaGetSymbolAddress((void**)&fuse, g_fuse);
    cudaGetSymbolAddress((void**)&u1,   g_u1);
    cudaGetSymbolAddress((void**)&wB,   g_wB);
    cudaGetSymbolAddress((void**)&wS,   g_wS);
    cudaGetSymbolAddress((void**)&wM,   g_wMLP);

    auto A4 = [](int x){ return ((x + 3) / 4) * 4; };
    const int SUP1_SMEM = (A4(3*18*37) + 9*3*32) * 4;
    const int UN1_SMEM  = (A4(8*18*37) + 9*8*32) * 4;
    const int MPN_SMEM  = (64 + 2*36*8*64 + 3*130*WST) * 4;   // 210112
    const int SUP2_SMEM = (64 + 1*36*4*64 + 3*130*WST) * 4;   // 99520

    cudaFuncSetAttribute(mlp_mma_kernel, cudaFuncAttributeMaxDynamicSharedMemorySize, MLP2_SMEM);
    cudaFuncSetAttribute(gconv_mma_kernel<2,8,true,false>,  cudaFuncAttributeMaxDynamicSharedMemorySize, MPN_SMEM);
    cudaFuncSetAttribute(gconv_mma_kernel<2,8,false,true>,  cudaFuncAttributeMaxDynamicSharedMemorySize, MPN_SMEM);
    cudaFuncSetAttribute(gconv_mma_kernel<1,4,false,false>, cudaFuncAttributeMaxDynamicSharedMemorySize, SUP2_SMEM);

    // 0. weight preps
    wprep_kernel<<<144, 256>>>(k_mpn1, k_mpn2);
    wprep_sup_kernel<<<36, 256>>>(k_sup2);
    wprep_mlp_kernel<<<152, 256>>>(W1, W2, W3, W4);
    // 1. MLP (mma tf32) -> feat (masked, stride 32)
    mlp_mma_kernel<<<2048, 256, MLP2_SMEM>>>(ray, zbufs, b1, b2, b3, b4, wM, feat);
    // 2. sup conv1 (fp32): 3->32 relu -> t1
    conv3x3_kernel<3,3,32,true><<<dim3(16,32,8), 256, SUP1_SMEM>>>(
        colors, k_sup1, b_sup1, t1, 0, 3*KK, 3, HWp*32, 32, 0);
    // 3. sup conv2 (mma tf32): 32->32 -> fc (stride 32)
    gconv_mma_kernel<1,4,false,false><<<dim3(4,512), 256, SUP2_SMEM>>>(
        t1, nullptr, 32, wS, b_sup2, fc, 32, nullptr, nullptr);
    // 4. mpn conv1 (mma tf32): [feat|fc] -> t2 (+bias relu, stride 64)
    gconv_mma_kernel<2,8,true,false><<<dim3(4,512), 256, MPN_SMEM>>>(
        feat, fc, 32, wB, b_mpn1, t2, 64, nullptr, nullptr);
    // 5. mpn conv2 (mma tf32) + sigmoid + cumprod composite -> fuse
    gconv_mma_kernel<2,8,false,true><<<dim3(4,512), 256, MPN_SMEM>>>(
        t2, t2 + 32, 64, wB + 36864, b_mpn2, fuse, 0, feat, fc);
    // 6. unet conv1 (fp32): 8->32 relu -> u1
    conv3x3_kernel<8,8,32,true><<<dim3(16,32,1), 256, UN1_SMEM>>>(
        fuse, k_un1, b_un1, u1, 0, KK, 0, 0, 32, 0);
    // 7. unet conv2: 32->3 -> img
    unet2_kernel<<<dim3(32,32,1), 256>>>(u1, k_un2, b_un2, (float*)d_out);
}

// round 9
// speedup vs baseline: 3.2198x; 1.0022x over previous
#include <cuda_runtime.h>
#include <cstddef>
#include <cstdint>

#define Hh 512
#define Ww 512
#define KK 8
#define HWp (Hh*Ww)

typedef unsigned long long ull;

__device__ float g_t1[KK * HWp * 32];     // sup1 out
__device__ float g_feat[KK * HWp * 32];   // MLP out (masked)
__device__ float g_fc[KK * HWp * 32];     // sup2 out
__device__ float g_t2[KK * HWp * 64];     // mpn1 out
__device__ float g_fuse[HWp * KK];
__device__ float g_u1[HWp * 32];
__device__ float g_wB[2 * 36864];   // prepped MPN weights (tf32 bits)
__device__ float g_wS[9216];        // prepped sup2 weights (tf32 bits)
__device__ float g_wMLP[38912];     // prepped MLP weights (tf32 bits)

// ---------------- packed fp32x2 helpers ----------------
__device__ __forceinline__ ull pack2(float v) {
    ull r; asm("mov.b64 %0, {%1, %1};" : "=l"(r) : "f"(v)); return r;
}
__device__ __forceinline__ float2 unpack2(ull v) {
    float2 f; asm("mov.b64 {%0, %1}, %2;" : "=f"(f.x), "=f"(f.y) : "l"(v)); return f;
}
__device__ __forceinline__ void fma2(ull &d, ull a, ull b) {
    asm("fma.rn.f32x2 %0, %1, %2, %0;" : "+l"(d) : "l"(a), "l"(b));
}
__device__ __forceinline__ float to_tf32(float v) {
    uint32_t o; asm("cvt.rna.tf32.f32 %0, %1;" : "=r"(o) : "f"(v));
    return __uint_as_float(o);
}

// ---------------- warp mma tf32 m16n8k8 ----------------
__device__ __forceinline__ void mma_tf32(float* c,
                                         float a0, float a1, float a2, float a3,
                                         float b0, float b1)
{
    asm volatile(
        "mma.sync.aligned.m16n8k8.row.col.f32.tf32.tf32.f32 "
        "{%0,%1,%2,%3}, {%4,%5,%6,%7}, {%8,%9}, {%0,%1,%2,%3};"
        : "+f"(c[0]), "+f"(c[1]), "+f"(c[2]), "+f"(c[3])
        : "r"(__float_as_uint(a0)), "r"(__float_as_uint(a1)),
          "r"(__float_as_uint(a2)), "r"(__float_as_uint(a3)),
          "r"(__float_as_uint(b0)), "r"(__float_as_uint(b1)));
}

// =======================================================================
// Weight preps
// =======================================================================
__global__ void wprep_kernel(const float* __restrict__ w1, const float* __restrict__ w2)
{
    int i = blockIdx.x * 256 + threadIdx.x;
    if (i >= 36864) return;
    int s   = i & 1;
    int c   = (i >> 1) & 3;
    int co  = (i >> 3) & 63;
    int blk = i >> 9;
    int g   = blk & 3;
    int ht  = blk >> 2;
    int h   = ht / 9, tap = ht - h * 9;
    int cin = h * 32 + g * 8 + c + s * 4;
    int src = (tap * 64 + cin) * 64 + co;
    g_wB[i]         = to_tf32(w1[src]);
    g_wB[36864 + i] = to_tf32(w2[src]);
}

__global__ void wprep_sup_kernel(const float* __restrict__ w)
{
    int i = blockIdx.x * 256 + threadIdx.x;
    if (i >= 9216) return;
    int s   = i & 1;
    int c   = (i >> 1) & 3;
    int co  = (i >> 3) & 31;
    int blk = i >> 8;
    int g   = blk & 3;
    int tap = blk >> 2;
    int cin = g * 8 + c + s * 4;
    g_wS[i] = to_tf32(w[(tap * 32 + cin) * 32 + co]);
}

#define MW1 0
#define MW2 1024
#define MW3 17408
#define MW4 34816
__global__ void wprep_mlp_kernel(const float* __restrict__ W1, const float* __restrict__ W2,
                                 const float* __restrict__ W3, const float* __restrict__ W4)
{
    int i = blockIdx.x * 256 + threadIdx.x;
    if (i >= 38912) return;
    int base, Kin, N; const float* W;
    if (i < MW2)      { base = MW1; Kin = 3;   N = 128; W = W1; }
    else if (i < MW3) { base = MW2; Kin = 128; N = 128; W = W2; }
    else if (i < MW4) { base = MW3; Kin = 131; N = 128; W = W3; }
    else              { base = MW4; Kin = 128; N = 32;  W = W4; }
    int r  = i - base;
    int s  = r & 1;
    int cq = (r >> 1) & 3;
    int n  = (r >> 3) % N;
    int ks = (r >> 3) / N;
    int k  = ks * 8 + cq + s * 4;
    g_wMLP[i] = (k < Kin) ? to_tf32(W[k * N + n]) : 0.f;
}

// =======================================================================
// MLP via mma.sync tf32, B-in-registers / K-interleaved activations.
// Warp w: couts (w&3)*32 (NCG=4), m-tiles (w>>2)*4..+4.
// Act layout: sample row (stride AST=168), k at pos g*8 + c*2 + s
// (k = g*8 + c + s*4) -> A fragment = 2x LDS.64, conflict-free.
// =======================================================================
#define AST 168
#define MLP2_SMEM ((2*128*AST + 416 + 128) * 4)

template<int KS>
__device__ __forceinline__ void mlp_layer2(const float* __restrict__ ain,
                                           const float* __restrict__ wg,
                                           const float* __restrict__ bia,
                                           float* __restrict__ aout,
                                           int nb, int mt0, int r, int cq)
{
    float2 bf[KS][4];
#pragma unroll
    for (int ks = 0; ks < KS; ks++)
#pragma unroll
        for (int cg = 0; cg < 4; cg++)
            bf[ks][cg] = __ldg((const float2*)wg + ((size_t)ks * 128 + nb + cg * 8 + r) * 4 + cq);

    const int pe = (cq & 1) * 4 + (cq >> 1);   // {0,4,1,5}
    const int po = pe + 2;                      // {2,6,3,7}
#pragma unroll
    for (int i = 0; i < 4; i++) {
        const int mt = mt0 + i;
        float c[4][4];
#pragma unroll
        for (int cg = 0; cg < 4; cg++)
            c[cg][0] = c[cg][1] = c[cg][2] = c[cg][3] = 0.f;
        const float* abase = ain + (mt * 16 + r) * AST + cq * 2;
#pragma unroll
        for (int ks = 0; ks < KS; ks++) {
            float2 a01 = *(const float2*)(abase + ks * 8);
            float2 a23 = *(const float2*)(abase + 8 * AST + ks * 8);
#pragma unroll
            for (int cg = 0; cg < 4; cg++)
                mma_tf32(c[cg], a01.x, a23.x, a01.y, a23.y, bf[ks][cg].x, bf[ks][cg].y);
        }
        float* obase = aout + (mt * 16 + r) * AST;
#pragma unroll
        for (int cg = 0; cg < 4; cg++) {
            int n  = nb + cg * 8 + cq * 2;
            int g8 = nb + cg * 8;
            float b0 = bia[n], b1 = bia[n + 1];
            obase[g8 + pe]           = to_tf32(fmaxf(c[cg][0] + b0, 0.f));
            obase[g8 + po]           = to_tf32(fmaxf(c[cg][1] + b1, 0.f));
            obase[8 * AST + g8 + pe] = to_tf32(fmaxf(c[cg][2] + b0, 0.f));
            obase[8 * AST + g8 + po] = to_tf32(fmaxf(c[cg][3] + b1, 0.f));
        }
    }
}

__global__ __launch_bounds__(256, 1)
void mlp_mma_kernel(const float* __restrict__ ray, const float* __restrict__ zb,
                    const float* __restrict__ b1, const float* __restrict__ b2,
                    const float* __restrict__ b3, const float* __restrict__ b4,
                    const float* __restrict__ wmlp, float* __restrict__ feat)
{
    extern __shared__ float sh[];
    float* buf0  = sh;                   // input / L2 out / L3 in (136 pos + dirs)
    float* buf1  = sh + 128 * AST;       // L1 out / L3 out
    float* sbias = sh + 2 * 128 * AST;
    float* smask = sbias + 416;

    const int tid = threadIdx.x;
    const int wrp = tid >> 5, lane = tid & 31;
    const int r = lane >> 2, cq = lane & 3;
    const int nb  = (wrp & 3) * 32;
    const int mt0 = (wrp >> 2) * 4;

    if (tid < 128) { sbias[tid] = b1[tid]; sbias[128 + tid] = b2[tid]; sbias[256 + tid] = b3[tid]; }
    if (tid < 32)  sbias[384 + tid] = b4[tid];
    __syncthreads();

    const int NT = (KK * HWp) / 128;
    for (int t = blockIdx.x; t < NT; t += gridDim.x) {
        if (tid < 128) {
            int sid = t * 128 + tid;
            int kk  = sid / HWp;
            int pix = sid - kk * HWp;
            const float* rp = ray + (size_t)pix * 7;
            float z  = zb[(size_t)pix * KK + kk];
            float tt = z / rp[6];
            float* A = buf0 + tid * AST;
            // group 0: k=0,1,2 at pos 0,2,4 (k+4 slots & k=3 zeroed)
            A[0] = to_tf32(rp[0] + rp[3] * tt); A[1] = 0.f;
            A[2] = to_tf32(rp[1] + rp[4] * tt); A[3] = 0.f;
            A[4] = to_tf32(rp[2] + rp[5] * tt); A[5] = 0.f;
            A[6] = 0.f; A[7] = 0.f;
            // group 16: dirs k=128,129,130 at pos 128,130,132
            A[128] = to_tf32(rp[3]); A[129] = 0.f;
            A[130] = to_tf32(rp[4]); A[131] = 0.f;
            A[132] = to_tf32(rp[5]); A[133] = 0.f;
            A[134] = 0.f; A[135] = 0.f;
            smask[tid] = (z > 0.f) ? 1.f : 0.f;
        }
        __syncthreads();
        mlp_layer2<1>(buf0, wmlp + MW1, sbias,        buf1, nb, mt0, r, cq);
        __syncthreads();
        mlp_layer2<16>(buf1, wmlp + MW2, sbias + 128, buf0, nb, mt0, r, cq);
        __syncthreads();
        mlp_layer2<17>(buf0, wmlp + MW3, sbias + 256, buf1, nb, mt0, r, cq);
        __syncthreads();
        // L4: K=128, N=32, plain masked store to feat
        {
            const int nb4 = (wrp & 1) * 16;
            float2 bf[16][2];
#pragma unroll
            for (int ks = 0; ks < 16; ks++)
#pragma unroll
                for (int cg = 0; cg < 2; cg++)
                    bf[ks][cg] = __ldg((const float2*)(wmlp + MW4)
                                       + ((size_t)ks * 32 + nb4 + cg * 8 + r) * 4 + cq);
#pragma unroll
            for (int half = 0; half < 2; half++) {
                const int mt = (wrp >> 1) + half * 4;
                float c[2][4];
#pragma unroll
                for (int cg = 0; cg < 2; cg++)
                    c[cg][0] = c[cg][1] = c[cg][2] = c[cg][3] = 0.f;
                const float* abase = buf1 + (mt * 16 + r) * AST + cq * 2;
#pragma unroll
                for (int ks = 0; ks < 16; ks++) {
                    float2 a01 = *(const float2*)(abase + ks * 8);
                    float2 a23 = *(const float2*)(abase + 8 * AST + ks * 8);
#pragma unroll
                    for (int cg = 0; cg < 2; cg++)
                        mma_tf32(c[cg], a01.x, a23.x, a01.y, a23.y, bf[ks][cg].x, bf[ks][cg].y);
                }
                const int m_lo = mt * 16 + r;
                float mf0 = smask[m_lo], mf8 = smask[m_lo + 8];
                size_t s0 = (size_t)t * 128 + m_lo;
#pragma unroll
                for (int cg = 0; cg < 2; cg++) {
                    int n = nb4 + cg * 8 + cq * 2;
                    float b0 = sbias[384 + n], b1v = sbias[384 + n + 1];
                    *(float2*)(feat + s0 * 32 + n) =
                        make_float2((c[cg][0] + b0) * mf0, (c[cg][1] + b1v) * mf0);
                    *(float2*)(feat + (s0 + 8) * 32 + n) =
                        make_float2((c[cg][2] + b0) * mf8, (c[cg][3] + b1v) * mf8);
                }
            }
        }
        __syncthreads();
    }
}

// =======================================================================
// Generalized 3x3 conv via mma.sync tf32 (unchanged R8)
// =======================================================================
#define WST 40

template<int NH, int NCG, bool RELU, bool FUSE>
__global__ __launch_bounds__(256, 1)
void gconv_mma_kernel(const float* __restrict__ in0, const float* __restrict__ in1,
                      int pixst,
                      const float* __restrict__ wB, const float* __restrict__ bias,
                      float* __restrict__ out, int ost,
                      const float* __restrict__ fm0, const float* __restrict__ fm1)
{
    extern __shared__ float sh[];
    float* s_bias = sh;
    float* s_w    = sh + 64;
    float* s_a    = sh + 64 + NH * 36 * NCG * 64;
    float* s_l    = s_a;

    const int tid  = threadIdx.x;
    const int wrp  = tid >> 5, lane = tid & 31;
    const int r    = lane >> 2, cq = lane & 3;
    const int gx   = blockIdx.x * 128;
    const int y    = blockIdx.y;

    {
        const float4* src = (const float4*)wB;
        float4* dst = (float4*)s_w;
        for (int i = tid; i < NH * 36 * NCG * 16; i += 256) dst[i] = src[i];
        if (tid < NCG * 8) s_bias[tid] = bias[tid];
    }
    __syncthreads();

    float bia[NCG][2];
#pragma unroll
    for (int cg = 0; cg < NCG; cg++) {
        bia[cg][0] = s_bias[cg * 8 + cq * 2];
        bia[cg][1] = s_bias[cg * 8 + cq * 2 + 1];
    }

    for (int k = 0; k < KK; k++) {
        float c[NCG][4];
#pragma unroll
        for (int cg = 0; cg < NCG; cg++) {
            c[cg][0] = bia[cg][0]; c[cg][1] = bia[cg][1];
            c[cg][2] = bia[cg][0]; c[cg][3] = bia[cg][1];
        }
#pragma unroll 1
        for (int h = 0; h < NH; h++) {
            const float* inb = (h == 0 ? in0 : in1) + (size_t)k * HWp * pixst;
            for (int it = tid; it < 1560; it += 256) {
                int ky  = it / 520;
                int rem = it - ky * 520;
                int p   = rem >> 2, g = rem & 3;
                int iy = y + ky - 1, ix = gx + p - 1;
                float4 lo = make_float4(0.f,0.f,0.f,0.f);
                float4 hi = make_float4(0.f,0.f,0.f,0.f);
                if ((unsigned)iy < Hh && (unsigned)ix < Ww) {
                    const float* q = inb + ((size_t)iy * Ww + ix) * pixst + g * 8;
                    lo = *(const float4*)q;
                    hi = *(const float4*)(q + 4);
                }
                float* d = s_a + (ky * 130 + p) * WST + g * 8;
                d[0] = lo.x; d[1] = hi.x; d[2] = lo.y; d[3] = hi.y;
                d[4] = lo.z; d[5] = hi.z; d[6] = lo.w; d[7] = hi.w;
            }
            __syncthreads();
#pragma unroll
            for (int tap = 0; tap < 9; tap++) {
                const int ky = tap / 3, kx = tap - ky * 3;
#pragma unroll
                for (int g = 0; g < 4; g++) {
                    const float* ap = s_a + (ky * 130 + kx + wrp * 16 + r) * WST + g * 8 + cq * 2;
                    float a0 = ap[0],         a2 = ap[1];
                    float a1 = ap[8 * WST],   a3 = ap[8 * WST + 1];
                    const float* wp = s_w + ((h * 9 + tap) * 4 + g) * (NCG * 64) + r * 8 + cq * 2;
#pragma unroll
                    for (int cg = 0; cg < NCG; cg++) {
                        float b0 = wp[cg * 64], b1 = wp[cg * 64 + 1];
                        mma_tf32(c[cg], a0, a1, a2, a3, b0, b1);
                    }
                }
            }
            __syncthreads();
        }

        if (!FUSE) {
            const size_t pixbase = (size_t)k * HWp + (size_t)y * Ww + gx + wrp * 16;
            float* o0 = out + (pixbase + r) * ost;
            float* o1 = out + (pixbase + r + 8) * ost;
#pragma unroll
            for (int cg = 0; cg < NCG; cg++) {
                float2 v0, v1;
                if (RELU) {
                    v0 = make_float2(fmaxf(c[cg][0], 0.f), fmaxf(c[cg][1], 0.f));
                    v1 = make_float2(fmaxf(c[cg][2], 0.f), fmaxf(c[cg][3], 0.f));
                } else {
                    v0 = make_float2(c[cg][0], c[cg][1]);
                    v1 = make_float2(c[cg][2], c[cg][3]);
                }
                *(float2*)(o0 + cg * 8 + cq * 2) = v0;
                *(float2*)(o1 + cg * 8 + cq * 2) = v1;
            }
        } else {
            const int p0 = wrp * 16 + r;
#pragma unroll
            for (int cg = 0; cg < NCG; cg++) {
                float* l0 = s_l + p0 * 65 + cg * 8 + cq * 2;
                l0[0] = c[cg][0]; l0[1] = c[cg][1];
                float* l1 = s_l + (p0 + 8) * 65 + cg * 8 + cq * 2;
                l1[0] = c[cg][2]; l1[1] = c[cg][3];
            }
            __syncthreads();
            if (tid < 128) {
                const int px = tid;
                const size_t pix = (size_t)y * Ww + gx + px;
                const float4* fa = (const float4*)(fm0 + ((size_t)k * HWp + pix) * 32);
                const float4* fb = (const float4*)(fm1 + ((size_t)k * HWp + pix) * 32);
                const float* lp = s_l + px * 65;
                float alpha = 1.f, fs = 0.f;
#pragma unroll
                for (int i = 0; i < 16; i++) {
                    float4 fv = (i < 8) ? __ldg(&fa[i]) : __ldg(&fb[i - 8]);
                    float l0 = lp[4*i], l1 = lp[4*i+1], l2 = lp[4*i+2], l3 = lp[4*i+3];
                    float m0 = 1.f / (1.f + __expf(-l0));
                    fs += fv.x * m0 * alpha; alpha *= (1.f - m0);
                    float m1 = 1.f / (1.f + __expf(-l1));
                    fs += fv.y * m1 * alpha; alpha *= (1.f - m1);
                    float m2 = 1.f / (1.f + __expf(-l2));
                    fs += fv.z * m2 * alpha; alpha *= (1.f - m2);
                    float m3 = 1.f / (1.f + __expf(-l3));
                    fs += fv.w * m3 * alpha; alpha *= (1.f - m3);
                }
                out[pix * KK + k] = fs;
            }
            __syncthreads();
        }
    }
}

// =======================================================================
// Direct 3x3 conv (fp32 FFMA2) — sup1/un1 (unchanged)
// =======================================================================
template<int CIN, int CHUNK, int COUT, bool RELU>
__global__ __launch_bounds__(256, 2)
void conv3x3_kernel(const float* __restrict__ in, const float* __restrict__ wgt,
                    const float* __restrict__ bias, float* __restrict__ out,
                    int in_batch_stride, int in_pix_stride, int in_ch_per_n,
                    int out_batch_stride, int out_pix_stride, int out_ch_off)
{
    constexpr int NCG   = COUT / 16;
    constexpr int SLOTS = 256 / NCG;
    constexpr int TY    = SLOTS / 8;
    constexpr int HY    = TY + 2;
    constexpr int RS    = 37;
    constexpr int SIN   = ((CHUNK * HY * RS + 3) / 4) * 4;

    extern __shared__ float sh[];
    float* s_in = sh;
    float* s_w  = sh + SIN;

    const int tid  = threadIdx.x;
    const int cg   = tid / SLOTS;
    const int slot = tid % SLOTS;
    const int sx   = (slot & 7) * 4;
    const int sy   = slot >> 3;
    const int gx = blockIdx.x * 32, gy = blockIdx.y * TY;
    const int n  = blockIdx.z;

    const float* inb = in + (size_t)n * in_batch_stride;
    const int choff_n = n * in_ch_per_n;

    ull acc[4][8];
    {
        const ull* b2 = (const ull*)(bias + cg * 16);
#pragma unroll
        for (int j = 0; j < 8; j++) {
            ull bv = __ldg(&b2[j]);
#pragma unroll
            for (int p = 0; p < 4; p++) acc[p][j] = bv;
        }
    }
    for (int c0 = 0; c0 < CIN; c0 += CHUNK) {
        for (int idx = tid; idx < CHUNK * HY * 34; idx += 256) {
            int c   = idx / (HY * 34);
            int rem = idx - c * (HY * 34);
            int rr  = rem / 34;
            int j   = rem - rr * 34;
            int iy = gy - 1 + rr, ix = gx - 1 + j;
            float v = 0.f;
            if ((unsigned)iy < Hh && (unsigned)ix < Ww)
                v = inb[(size_t)(iy * Ww + ix) * in_pix_stride + choff_n + c0 + c];
            s_in[(c * HY + rr) * RS + j] = v;
        }
        for (int idx = tid; idx < 9 * CHUNK * COUT; idx += 256) {
            int tap = idx / (CHUNK * COUT);
            int rem = idx - tap * (CHUNK * COUT);
            int c   = rem / COUT;
            int co  = rem - c * COUT;
            s_w[idx] = wgt[(size_t)(tap * CIN + c0 + c) * COUT + co];
        }
        __syncthreads();
#pragma unroll
        for (int ky = 0; ky < 3; ky++) {
#pragma unroll
            for (int c = 0; c < CHUNK; c++) {
                const float* ip = s_in + ((c * HY) + sy + ky) * RS + sx;
                float a[6];
#pragma unroll
                for (int i = 0; i < 6; i++) a[i] = ip[i];
#pragma unroll
                for (int kx = 0; kx < 3; kx++) {
                    const ulonglong2* wp = (const ulonglong2*)
                        (s_w + ((ky * 3 + kx) * CHUNK + c) * COUT + cg * 16);
                    ulonglong2 w0 = wp[0], w1 = wp[1], w2 = wp[2], w3 = wp[3];
#pragma unroll
                    for (int p = 0; p < 4; p++) {
                        ull a2 = pack2(a[kx + p]);
                        fma2(acc[p][0], a2, w0.x); fma2(acc[p][1], a2, w0.y);
                        fma2(acc[p][2], a2, w1.x); fma2(acc[p][3], a2, w1.y);
                        fma2(acc[p][4], a2, w2.x); fma2(acc[p][5], a2, w2.y);
                        fma2(acc[p][6], a2, w3.x); fma2(acc[p][7], a2, w3.y);
                    }
                }
            }
        }
        __syncthreads();
    }
#pragma unroll
    for (int p = 0; p < 4; p++) {
        float* op = out + (size_t)n * out_batch_stride
                        + (size_t)((gy + sy) * Ww + gx + sx + p) * out_pix_stride
                        + out_ch_off + cg * 16;
#pragma unroll
        for (int i = 0; i < 4; i++) {
            float2 v0 = unpack2(acc[p][2*i]), v1 = unpack2(acc[p][2*i+1]);
            float4 o = make_float4(v0.x, v0.y, v1.x, v1.y);
            if (RELU) { o.x=fmaxf(o.x,0.f); o.y=fmaxf(o.y,0.f); o.z=fmaxf(o.z,0.f); o.w=fmaxf(o.w,0.f); }
            *(float4*)(op + 4*i) = o;
        }
    }
}

// =======================================================================
// unet conv2: 32 -> 3 (unchanged)
// =======================================================================
__global__ __launch_bounds__(256)
void unet2_kernel(const float* __restrict__ in, const float* __restrict__ wgt,
                  const float* __restrict__ bias, float* __restrict__ out)
{
    constexpr int CIN = 32, CHUNK = 16, SP = CHUNK + 1;
    __shared__ float s_in[324 * SP];
    __shared__ float s_w[9 * CHUNK * 3];

    const int tid = threadIdx.x;
    const int tx = tid & 15, ty = tid >> 4;
    const int gx = blockIdx.x * 16, gy = blockIdx.y * 16;

    float acc0 = __ldg(&bias[0]), acc1 = __ldg(&bias[1]), acc2 = __ldg(&bias[2]);

    for (int c0 = 0; c0 < CIN; c0 += CHUNK) {
        for (int idx = tid; idx < 324 * CHUNK; idx += 256) {
            int p = idx / CHUNK, c = idx - p * CHUNK;
            int py = p / 18, px = p - py * 18;
            int iy = gy - 1 + py, ix = gx - 1 + px;
            float v = 0.f;
            if ((unsigned)iy < Hh && (unsigned)ix < Ww)
                v = in[(size_t)(iy * Ww + ix) * CIN + c0 + c];
            s_in[p * SP + c] = v;
        }
        for (int idx = tid; idx < 9 * CHUNK * 3; idx += 256) {
            int tap = idx / (CHUNK * 3);
            int r   = idx - tap * (CHUNK * 3);
            int c   = r / 3, co = r - c * 3;
            s_w[idx] = wgt[(size_t)(tap * CIN + c0 + c) * 3 + co];
        }
        __syncthreads();
#pragma unroll
        for (int tap = 0; tap < 9; tap++) {
            int ky = tap / 3, kx = tap - ky * 3;
            const float* ip = s_in + ((ty + ky) * 18 + tx + kx) * SP;
            const float* wp = s_w + tap * CHUNK * 3;
#pragma unroll
            for (int c = 0; c < CHUNK; c++) {
                float a = ip[c];
                acc0 += a * wp[c*3 + 0];
                acc1 += a * wp[c*3 + 1];
                acc2 += a * wp[c*3 + 2];
            }
        }
        __syncthreads();
    }
    float* op = out + (size_t)((gy + ty) * Ww + gx + tx) * 3;
    op[0] = acc0; op[1] = acc1; op[2] = acc2;
}

// =======================================================================
extern "C" void kernel_launch(void* const* d_in, const int* in_sizes, int n_in,
                              void* d_out, int out_size)
{
    const float* colors = (const float*)d_in[0];
    const float* ray    = (const float*)d_in[1];
    const float* zbufs  = (const float*)d_in[2];
    const float* W1 = (const float*)d_in[3];  const float* b1 = (const float*)d_in[4];
    const float* W2 = (const float*)d_in[5];  const float* b2 = (const float*)d_in[6];
    const float* W3 = (const float*)d_in[7];  const float* b3 = (const float*)d_in[8];
    const float* W4 = (const float*)d_in[9];  const float* b4 = (const float*)d_in[10];
    const float* k_sup1 = (const float*)d_in[11]; const float* b_sup1 = (const float*)d_in[12];
    const float* k_sup2 = (const float*)d_in[13]; const float* b_sup2 = (const float*)d_in[14];
    const float* k_mpn1 = (const float*)d_in[15]; const float* b_mpn1 = (const float*)d_in[16];
    const float* k_mpn2 = (const float*)d_in[17]; const float* b_mpn2 = (const float*)d_in[18];
    const float* k_un1  = (const float*)d_in[19]; const float* b_un1  = (const float*)d_in[20];
    const float* k_un2  = (const float*)d_in[21]; const float* b_un2  = (const float*)d_in[22];

    float *t1, *feat, *fc, *t2, *fuse, *u1, *wB, *wS, *wM;
    cudaGetSymbolAddress((void**)&t1,   g_t1);
    cudaGetSymbolAddress((void**)&feat, g_feat);
    cudaGetSymbolAddress((void**)&fc,   g_fc);
    cudaGetSymbolAddress((void**)&t2,   g_t2);
    cudaGetSymbolAddress((void**)&fuse, g_fuse);
    cudaGetSymbolAddress((void**)&u1,   g_u1);
    cudaGetSymbolAddress((void**)&wB,   g_wB);
    cudaGetSymbolAddress((void**)&wS,   g_wS);
    cudaGetSymbolAddress((void**)&wM,   g_wMLP);

    auto A4 = [](int x){ return ((x + 3) / 4) * 4; };
    const int SUP1_SMEM = (A4(3*18*37) + 9*3*32) * 4;
    const int UN1_SMEM  = (A4(8*18*37) + 9*8*32) * 4;
    const int MPN_SMEM  = (64 + 2*36*8*64 + 3*130*WST) * 4;
    const int SUP2_SMEM = (64 + 1*36*4*64 + 3*130*WST) * 4;

    cudaFuncSetAttribute(mlp_mma_kernel, cudaFuncAttributeMaxDynamicSharedMemorySize, MLP2_SMEM);
    cudaFuncSetAttribute(gconv_mma_kernel<2,8,true,false>,  cudaFuncAttributeMaxDynamicSharedMemorySize, MPN_SMEM);
    cudaFuncSetAttribute(gconv_mma_kernel<2,8,false,true>,  cudaFuncAttributeMaxDynamicSharedMemorySize, MPN_SMEM);
    cudaFuncSetAttribute(gconv_mma_kernel<1,4,false,false>, cudaFuncAttributeMaxDynamicSharedMemorySize, SUP2_SMEM);

    // 0. weight preps
    wprep_kernel<<<144, 256>>>(k_mpn1, k_mpn2);
    wprep_sup_kernel<<<36, 256>>>(k_sup2);
    wprep_mlp_kernel<<<152, 256>>>(W1, W2, W3, W4);
    // 1. MLP (mma tf32) -> feat (masked, stride 32)
    mlp_mma_kernel<<<2048, 256, MLP2_SMEM>>>(ray, zbufs, b1, b2, b3, b4, wM, feat);
    // 2. sup conv1 (fp32): 3->32 relu -> t1
    conv3x3_kernel<3,3,32,true><<<dim3(16,32,8), 256, SUP1_SMEM>>>(
        colors, k_sup1, b_sup1, t1, 0, 3*KK, 3, HWp*32, 32, 0);
    // 3. sup conv2 (mma tf32): 32->32 -> fc (stride 32)
    gconv_mma_kernel<1,4,false,false><<<dim3(4,512), 256, SUP2_SMEM>>>(
        t1, nullptr, 32, wS, b_sup2, fc, 32, nullptr, nullptr);
    // 4. mpn conv1 (mma tf32): [feat|fc] -> t2 (+bias relu, stride 64)
    gconv_mma_kernel<2,8,true,false><<<dim3(4,512), 256, MPN_SMEM>>>(
        feat, fc, 32, wB, b_mpn1, t2, 64, nullptr, nullptr);
    // 5. mpn conv2 (mma tf32) + sigmoid + cumprod composite -> fuse
    gconv_mma_kernel<2,8,false,true><<<dim3(4,512), 256, MPN_SMEM>>>(
        t2, t2 + 32, 64, wB + 36864, b_mpn2, fuse, 0, feat, fc);
    // 6. unet conv1 (fp32): 8->32 relu -> u1
    conv3x3_kernel<8,8,32,true><<<dim3(16,32,1), 256, UN1_SMEM>>>(
        fuse, k_un1, b_un1, u1, 0, KK, 0, 0, 32, 0);
    // 7. unet conv2: 32->3 -> img
    unet2_kernel<<<dim3(32,32,1), 256>>>(u1, k_un2, b_un2, (float*)d_out);
}